// round 12
// baseline (speedup 1.0000x reference)
#include <cuda_runtime.h>
#include <cuda_fp16.h>
#include <math.h>
#include <stdint.h>

#define N_ATOMSC 100000
#define M_NBR    12
#define ORIG     92
#define NBRF     41
#define AF       64
#define G1       128
#define NM       (N_ATOMSC*M_NBR)
#define OUTD     128
#define NCRY     2000
#define APC      50
#define EPSL     1e-5f

// ---------------- device scratch ----------------------------------------
__device__ float   g_x[N_ATOMSC*AF];
__device__ float   g_P[N_ATOMSC*G1];
__device__ float   g_Q[N_ATOMSC*G1];
__device__ __half2 g_gated[(size_t)NM*(G1/2)];       // fp16 gated (307 MB)
__device__ __align__(16) __half2 g_Eh[(size_t)N_ATOMSC*256];  // packed E pairs (102 MB)
__device__ float   g_ns[N_ATOMSC*AF];
__device__ float   g_s1[G1], g_ss1[G1], g_a1[G1], g_b1[G1];
__device__ float   g_s2[AF], g_ss2[AF], g_a2[AF], g_b2[AF];

__device__ __forceinline__ float softplus_fast(float x){
    return fmaxf(x, 0.f) + __logf(1.f + __expf(-fabsf(x)));
}
__device__ __forceinline__ float sigmoid_tanh(float x){
    float t;
    asm("tanh.approx.f32 %0, %1;" : "=f"(t) : "f"(0.5f*x));
    return fmaf(0.5f, t, 0.5f);
}

// ---------------- E preconversion: float E -> packed half2 pairs ---------
__global__ void __launch_bounds__(256) kPrep(const float* __restrict__ E){
    int idx = blockIdx.x*256 + threadIdx.x;
    int atom = idx >> 8, o = idx & 255;
    if (o >= 252){ g_Eh[idx] = __float2half2_rn(0.f); return; }
    int r = o / 21, kp = o - r*21;
    size_t row = (size_t)atom*12 + r;
    float e0 = E[row*NBRF + kp*2];
    float e1 = (kp < 20) ? E[row*NBRF + kp*2 + 1] : 0.f;
    g_Eh[idx] = __floats2half2_rn(e0, e1);
}

// ---------------- embed: x = atom_fea @ W_embed + b ---------------------
__global__ void __launch_bounds__(256) kEmbed(const float* __restrict__ A,
                                              const float* __restrict__ W,
                                              const float* __restrict__ b){
    __shared__ float sW[ORIG*AF];
    __shared__ float sb_[AF];
    __shared__ float sIn[8][4*ORIG];
    int tid = threadIdx.x;
    for (int i = tid; i < ORIG*AF; i += 256) sW[i] = W[i];
    if (tid < AF) sb_[tid] = b[tid];
    __syncthreads();
    int warp = tid >> 5, lane = tid & 31;
    int gw = blockIdx.x*8 + warp, nw = gridDim.x*8;
    float b0 = sb_[lane*2], b1 = sb_[lane*2+1];
    for (int grp = gw; grp < N_ATOMSC/4; grp += nw){
        int base = grp*4;
        for (int i = lane; i < 4*ORIG; i += 32)
            sIn[warp][i] = A[base*ORIG + i];
        __syncwarp();
        float acc[4][2];
        #pragma unroll
        for (int r = 0; r < 4; r++){ acc[r][0] = b0; acc[r][1] = b1; }
        #pragma unroll 4
        for (int k = 0; k < ORIG; k++){
            float2 w = *(const float2*)&sW[k*AF + lane*2];
            #pragma unroll
            for (int r = 0; r < 4; r++){
                float xv = sIn[warp][r*ORIG + k];
                acc[r][0] = fmaf(xv, w.x, acc[r][0]);
                acc[r][1] = fmaf(xv, w.y, acc[r][1]);
            }
        }
        #pragma unroll
        for (int r = 0; r < 4; r++)
            *(float2*)&g_x[(base+r)*AF + lane*2] = make_float2(acc[r][0], acc[r][1]);
        __syncwarp();
    }
}

// ---------------- P/Q GEMM core (HFMA2, dual parity chains) --------------
__device__ __forceinline__ void pq_gemm_body(const uint4* sWq, const __half2* sXw,
                                             int base){
    __half2 z = __float2half2_rn(0.f);
    __half2 aA[2][4] = {{z,z,z,z},{z,z,z,z}};
    __half2 aB[2][4] = {{z,z,z,z},{z,z,z,z}};
    int lane = threadIdx.x & 31;
    #pragma unroll 4
    for (int kp = 0; kp < 32; kp++){
        uint4 wAu = sWq[(2*kp)*32 + lane];
        uint4 wBu = sWq[(2*kp+1)*32 + lane];
        __half2 wA[4] = {*(__half2*)&wAu.x, *(__half2*)&wAu.y,
                         *(__half2*)&wAu.z, *(__half2*)&wAu.w};
        __half2 wB[4] = {*(__half2*)&wBu.x, *(__half2*)&wBu.y,
                         *(__half2*)&wBu.z, *(__half2*)&wBu.w};
        #pragma unroll
        for (int a = 0; a < 2; a++){
            __half2 ep = sXw[a*33 + kp];
            __half2 eA = __low2half2(ep), eB = __high2half2(ep);
            #pragma unroll
            for (int c = 0; c < 4; c++){
                aA[a][c] = __hfma2(eA, wA[c], aA[a][c]);
                aB[a][c] = __hfma2(eB, wB[c], aB[a][c]);
            }
        }
    }
    #pragma unroll
    for (int a = 0; a < 2; a++){
        float2 f[4];
        #pragma unroll
        for (int c = 0; c < 4; c++)
            f[c] = __half22float2(__hadd2(aA[a][c], aB[a][c]));
        float* dst = (lane < 16) ? &g_P[(size_t)(base+a)*G1 + lane*8]
                                 : &g_Q[(size_t)(base+a)*G1 + (lane-16)*8];
        *(float4*)dst       = make_float4(f[0].x, f[0].y, f[1].x, f[1].y);
        *(float4*)(dst + 4) = make_float4(f[2].x, f[2].y, f[3].x, f[3].y);
    }
}

__device__ __forceinline__ void load_pq_weights(uint4* sWq, const float* Wf){
    __half2* sWh = (__half2*)sWq;
    int tid = threadIdx.x;
    for (int i = tid; i < 64*128; i += 256){
        int k = i >> 7, cp = i & 127;
        int c0 = cp*2, c1 = cp*2 + 1;
        float w0 = (c0 < G1) ? Wf[k*G1 + c0] : Wf[(AF + k)*G1 + (c0 - G1)];
        float w1 = (c1 < G1) ? Wf[k*G1 + c1] : Wf[(AF + k)*G1 + (c1 - G1)];
        sWh[k*128 + cp] = __floats2half2_rn(w0, w1);
    }
}

// ---------------- standalone P/Q GEMM (layer 0) ---------------------------
__global__ void __launch_bounds__(256) kPQ2(const float* __restrict__ Wf){
    __shared__ uint4 sWq[64*32];
    __shared__ __half2 sX[8][2*33];
    int tid = threadIdx.x, wid = tid >> 5, lane = tid & 31;
    load_pq_weights(sWq, Wf);
    __syncthreads();
    int gw = blockIdx.x*8 + wid, nw = gridDim.x*8;
    for (int grp = gw; grp < N_ATOMSC/2; grp += nw){
        int base = grp*2;
        for (int i = lane; i < 64; i += 32){
            int a = i >> 5, kp = i & 31;
            sX[wid][a*33 + kp] = __floats2half2_rn(g_x[(base+a)*AF + kp*2],
                                                   g_x[(base+a)*AF + kp*2 + 1]);
        }
        __syncwarp();
        pq_gemm_body(sWq, sX[wid], base);
        __syncwarp();
    }
}

// ---------------- fused residual update + next-layer P/Q GEMM ------------
__global__ void __launch_bounds__(256) kUpdatePQ(const float* __restrict__ WfNext){
    __shared__ uint4 sWq[64*32];
    __shared__ __half2 sX[8][2*33];
    int tid = threadIdx.x, wid = tid >> 5, lane = tid & 31;
    load_pq_weights(sWq, WfNext);
    __syncthreads();
    int gw = blockIdx.x*8 + wid, nw = gridDim.x*8;
    for (int grp = gw; grp < N_ATOMSC/2; grp += nw){
        int base = grp*2;
        for (int i = lane; i < 64; i += 32){
            int a = i >> 5, kp = i & 31;
            size_t off = (size_t)(base+a)*AF + kp*2;
            float2 xv = *(const float2*)&g_x[off];
            float2 nv = *(const float2*)&g_ns[off];
            float2 a2 = *(const float2*)&g_a2[kp*2];
            float2 b2 = *(const float2*)&g_b2[kp*2];
            float x0 = softplus_fast(xv.x + fmaf(nv.x, a2.x, b2.x));
            float x1 = softplus_fast(xv.y + fmaf(nv.y, a2.y, b2.y));
            *(float2*)&g_x[off] = make_float2(x0, x1);
            sX[wid][a*33 + kp] = __floats2half2_rn(x0, x1);
        }
        __syncwarp();
        pq_gemm_body(sWq, sX[wid], base);
        __syncwarp();
    }
}

// ---------------- edge kernel: 12 rows/warp, merged chains, 128-thr ------
__global__ void __launch_bounds__(128, 6) kEdgeH(const int*   __restrict__ NI,
                                                 const float* __restrict__ Wf,
                                                 const float* __restrict__ bf){
    __shared__ uint2 sWq[42*32];                  // 10752 B
    __shared__ float sb[G1], sS[G1], sQ[G1];
    __shared__ __align__(16) __half2 sE[4][256];  // 4096 B (64 uint4 per warp)
    int tid = threadIdx.x, wid = tid >> 5, lane = tid & 31;
    const float* WfE = Wf + 128*G1;
    __half2* sWh = (__half2*)sWq;
    for (int i = tid; i < NBRF*64; i += 128){
        int k = i >> 6, cp = i & 63;
        sWh[k*64 + cp] = __floats2half2_rn(WfE[k*G1 + cp*2], WfE[k*G1 + cp*2 + 1]);
    }
    for (int i = NBRF*64 + tid; i < 42*64; i += 128) sWh[i] = __float2half2_rn(0.f);
    if (tid < G1){ sb[tid] = bf[tid]; sS[tid] = 0.f; sQ[tid] = 0.f; }
    __syncthreads();

    float4 bb = *(const float4*)&sb[lane*4];
    float cs[4] = {0,0,0,0}, cq[4] = {0,0,0,0};

    const uint4* Eh4 = (const uint4*)g_Eh;        // 64 uint4 per atom
    int gw = blockIdx.x*4 + wid, nw = gridDim.x*4;
    uint4 er0, er1;
    if (gw < N_ATOMSC){
        er0 = Eh4[(size_t)gw*64 + lane];
        er1 = Eh4[(size_t)gw*64 + 32 + lane];
    }

    for (int n = gw; n < N_ATOMSC; n += nw){
        ((uint4*)sE[wid])[lane]      = er0;
        ((uint4*)sE[wid])[lane + 32] = er1;
        __syncwarp();
        int nn = n + nw;
        if (nn < N_ATOMSC){
            er0 = Eh4[(size_t)nn*64 + lane];
            er1 = Eh4[(size_t)nn*64 + 32 + lane];
        }

        size_t rb = (size_t)n * 12;
        int4 j0 = *(const int4*)&NI[rb];
        int4 j1 = *(const int4*)&NI[rb + 4];
        int4 j2 = *(const int4*)&NI[rb + 8];
        int jj[12] = {j0.x,j0.y,j0.z,j0.w, j1.x,j1.y,j1.z,j1.w, j2.x,j2.y,j2.z,j2.w};
        float4 p = *(const float4*)&g_P[(size_t)n*G1 + lane*4];
        float4 pqb = make_float4(p.x + bb.x, p.y + bb.y, p.z + bb.z, p.w + bb.w);

        __half2 z = __float2half2_rn(0.f);
        __half2 acc[12][2];
        #pragma unroll
        for (int r = 0; r < 12; r++){ acc[r][0] = z; acc[r][1] = z; }
        #pragma unroll 3
        for (int kp = 0; kp < 21; kp++){
            uint2 wAu = sWq[(2*kp)*32 + lane];
            uint2 wBu = sWq[(2*kp+1)*32 + lane];
            __half2 wA0 = *(__half2*)&wAu.x, wA1 = *(__half2*)&wAu.y;
            __half2 wB0 = *(__half2*)&wBu.x, wB1 = *(__half2*)&wBu.y;
            #pragma unroll
            for (int r = 0; r < 12; r++){
                __half2 ep = sE[wid][r*21 + kp];
                __half2 eA = __low2half2(ep), eB = __high2half2(ep);
                acc[r][0] = __hfma2(eA, wA0, acc[r][0]);
                acc[r][1] = __hfma2(eA, wA1, acc[r][1]);
                acc[r][0] = __hfma2(eB, wB0, acc[r][0]);
                acc[r][1] = __hfma2(eB, wB1, acc[r][1]);
            }
        }
        #pragma unroll
        for (int r = 0; r < 12; r++){
            float4 q = *(const float4*)&g_Q[(size_t)jj[r]*G1 + lane*4];
            float2 f0 = __half22float2(acc[r][0]);
            float2 f1 = __half22float2(acc[r][1]);
            float v0 = f0.x + pqb.x + q.x;
            float v1 = f0.y + pqb.y + q.y;
            float v2 = f1.x + pqb.z + q.z;
            float v3 = f1.y + pqb.w + q.w;
            cs[0] += v0; cq[0] = fmaf(v0, v0, cq[0]);
            cs[1] += v1; cq[1] = fmaf(v1, v1, cq[1]);
            cs[2] += v2; cq[2] = fmaf(v2, v2, cq[2]);
            cs[3] += v3; cq[3] = fmaf(v3, v3, cq[3]);
            __half2 h0 = __floats2half2_rn(v0, v1);
            __half2 h1 = __floats2half2_rn(v2, v3);
            *(uint2*)&g_gated[(rb + r)*(G1/2) + lane*2] =
                make_uint2(*(unsigned*)&h0, *(unsigned*)&h1);
        }
        __syncwarp();
    }
    atomicAdd(&sS[lane*4+0], cs[0]); atomicAdd(&sQ[lane*4+0], cq[0]);
    atomicAdd(&sS[lane*4+1], cs[1]); atomicAdd(&sQ[lane*4+1], cq[1]);
    atomicAdd(&sS[lane*4+2], cs[2]); atomicAdd(&sQ[lane*4+2], cq[2]);
    atomicAdd(&sS[lane*4+3], cs[3]); atomicAdd(&sQ[lane*4+3], cq[3]);
    __syncthreads();
    if (tid < G1){
        atomicAdd(&g_s1[tid],  sS[tid]);
        atomicAdd(&g_ss1[tid], sQ[tid]);
    }
}

// ---------------- BN1 finalize -------------------------------------------
__global__ void kBN1(const float* __restrict__ gam, const float* __restrict__ bet){
    int f = threadIdx.x;
    float inv = 1.f / (float)NM;
    float m = g_s1[f]*inv;
    float v = g_ss1[f]*inv - m*m;
    float a = gam[f] * rsqrtf(v + EPSL);
    g_a1[f] = a;
    g_b1[f] = bet[f] - m*a;
    g_s1[f] = 0.f; g_ss1[f] = 0.f;
}

// ---------------- reduce: sigmoid*softplus over fp16 gated ----------------
__global__ void __launch_bounds__(256) kReduce(){
    __shared__ float rs[AF], rq[AF];
    int tid = threadIdx.x;
    int wid = tid >> 5, lane = tid & 31;
    if (tid < AF){ rs[tid] = 0.f; rq[tid] = 0.f; }
    __syncthreads();
    int f2 = lane*2;
    float A1x = g_a1[f2],    A1y = g_a1[f2+1];
    float B1x = g_b1[f2],    B1y = g_b1[f2+1];
    float A2x = g_a1[64+f2], A2y = g_a1[64+f2+1];
    float B2x = g_b1[64+f2], B2y = g_b1[64+f2+1];
    float s0=0,s1=0,q0=0,q1=0;
    int gw = blockIdx.x*8 + wid, nw = gridDim.x*8;
    for (int n = gw; n < N_ATOMSC; n += nw){
        const __half2* bh = g_gated + (size_t)n*(M_NBR*(G1/2)) + lane;
        float a0 = 0.f, a1 = 0.f;
        #pragma unroll
        for (int m = 0; m < M_NBR; m++){
            float2 zf = __half22float2(bh[m*64]);
            float2 zc = __half22float2(bh[m*64 + 32]);
            float xf0 = fmaf(zf.x, A1x, B1x);
            float xf1 = fmaf(zf.y, A1y, B1y);
            float xc0 = fmaf(zc.x, A2x, B2x);
            float xc1 = fmaf(zc.y, A2y, B2y);
            float sg0 = sigmoid_tanh(xf0);
            float sg1 = sigmoid_tanh(xf1);
            a0 = fmaf(sg0, softplus_fast(xc0), a0);
            a1 = fmaf(sg1, softplus_fast(xc1), a1);
        }
        *(float2*)&g_ns[(size_t)n*AF + f2] = make_float2(a0, a1);
        s0 += a0; q0 = fmaf(a0, a0, q0);
        s1 += a1; q1 = fmaf(a1, a1, q1);
    }
    atomicAdd(&rs[f2],   s0); atomicAdd(&rq[f2],   q0);
    atomicAdd(&rs[f2+1], s1); atomicAdd(&rq[f2+1], q1);
    __syncthreads();
    if (tid < AF){
        atomicAdd(&g_s2[tid],  rs[tid]);
        atomicAdd(&g_ss2[tid], rq[tid]);
    }
}

// ---------------- BN2 finalize ------------------------------------------
__global__ void kBN2(const float* __restrict__ gam, const float* __restrict__ bet){
    int f = threadIdx.x;
    float inv = 1.f / (float)N_ATOMSC;
    float m = g_s2[f]*inv;
    float v = g_ss2[f]*inv - m*m;
    float a = gam[f] * rsqrtf(v + EPSL);
    g_a2[f] = a;
    g_b2[f] = bet[f] - m*a;
    g_s2[f] = 0.f; g_ss2[f] = 0.f;
}

// ---------------- plain residual update (last layer) ---------------------
__global__ void __launch_bounds__(256) kUpdate(){
    int i4 = blockIdx.x*256 + threadIdx.x;
    int f = (i4 & 15) * 4;
    float4 xv = *(const float4*)&g_x[i4*4];
    float4 nv = *(const float4*)&g_ns[i4*4];
    float4 a2 = *(const float4*)&g_a2[f];
    float4 b2 = *(const float4*)&g_b2[f];
    float4 o;
    o.x = softplus_fast(xv.x + fmaf(nv.x, a2.x, b2.x));
    o.y = softplus_fast(xv.y + fmaf(nv.y, a2.y, b2.y));
    o.z = softplus_fast(xv.z + fmaf(nv.z, a2.z, b2.z));
    o.w = softplus_fast(xv.w + fmaf(nv.w, a2.w, b2.w));
    *(float4*)&g_x[i4*4] = o;
}

// ---------------- pool + FC + ReLU ---------------------------------------
__global__ void __launch_bounds__(128) kPool(const int* __restrict__ cidx,
                                             const float* __restrict__ Wp,
                                             const float* __restrict__ bp,
                                             float* __restrict__ out){
    __shared__ float sm[AF];
    int c = blockIdx.x, tid = threadIdx.x;
    if (tid < AF){
        float s = 0.f;
        #pragma unroll 5
        for (int a = 0; a < APC; a++){
            int idx = cidx[c*APC + a];
            s += g_x[idx*AF + tid];
        }
        sm[tid] = s * (1.f/(float)APC);
    }
    __syncthreads();
    float acc = bp[tid];
    #pragma unroll 8
    for (int k = 0; k < AF; k++)
        acc = fmaf(sm[k], Wp[k*OUTD + tid], acc);
    out[c*OUTD + tid] = fmaxf(acc, 0.f);
}

// ---------------- launcher ------------------------------------------------
extern "C" void kernel_launch(void* const* d_in, const int* in_sizes, int n_in,
                              void* d_out, int out_size){
    const float* atom_fea = (const float*)d_in[0];
    const float* nbr_fea  = (const float*)d_in[1];
    const int*   nbr_idx  = (const int*)  d_in[2];
    const int*   cidx     = (const int*)  d_in[3];
    const float* W_embed  = (const float*)d_in[4];
    const float* b_embed  = (const float*)d_in[5];
    const float* W_full   = (const float*)d_in[6];
    const float* b_full   = (const float*)d_in[7];
    const float* g1       = (const float*)d_in[8];
    const float* be1      = (const float*)d_in[9];
    const float* g2       = (const float*)d_in[10];
    const float* be2      = (const float*)d_in[11];
    const float* Wp       = (const float*)d_in[12];
    const float* bp       = (const float*)d_in[13];
    float* out = (float*)d_out;

    kEmbed<<<512, 256>>>(atom_fea, W_embed, b_embed);        // launch 0
    kPrep <<<N_ATOMSC, 256>>>(nbr_fea);                      // launch 1
    kPQ2  <<<592, 256>>>(W_full);                            // launch 2
    for (int l = 0; l < 3; l++){
        const float* Wf = W_full + (size_t)l * 169 * G1;
        kEdgeH <<<1184, 128>>>(nbr_idx, Wf, b_full + l*G1);  // l==0 -> launch 3
        kBN1   <<<1, 128>>>(g1 + l*G1, be1 + l*G1);
        kReduce<<<1024, 256>>>();
        kBN2   <<<1, 64>>>(g2 + l*AF, be2 + l*AF);
        if (l < 2){
            const float* WfN = W_full + (size_t)(l+1) * 169 * G1;
            kUpdatePQ<<<592, 256>>>(WfN);
        } else {
            kUpdate<<<(N_ATOMSC*AF/4)/256, 256>>>();
        }
    }
    kPool<<<NCRY, 128>>>(cidx, Wp, bp, out);
}

// round 13
// speedup vs baseline: 1.1197x; 1.1197x over previous
#include <cuda_runtime.h>
#include <cuda_fp16.h>
#include <math.h>
#include <stdint.h>

#define N_ATOMSC 100000
#define M_NBR    12
#define ORIG     92
#define NBRF     41
#define AF       64
#define G1       128
#define NM       (N_ATOMSC*M_NBR)
#define OUTD     128
#define NCRY     2000
#define APC      50
#define EPSL     1e-5f

// ---------------- device scratch ----------------------------------------
__device__ float   g_x[N_ATOMSC*AF];
__device__ float   g_P[N_ATOMSC*G1];
__device__ float   g_Q[N_ATOMSC*G1];
__device__ __half2 g_gated[(size_t)NM*(G1/2)];       // fp16 gated (307 MB)
__device__ __align__(16) __half2 g_Eh[(size_t)N_ATOMSC*256];  // packed E pairs (102 MB)
__device__ float   g_ns[N_ATOMSC*AF];
__device__ float   g_s1[G1], g_ss1[G1], g_a1[G1], g_b1[G1];
__device__ float   g_s2[AF], g_ss2[AF], g_a2[AF], g_b2[AF];

__device__ __forceinline__ float softplus_fast(float x){
    return fmaxf(x, 0.f) + __logf(1.f + __expf(-fabsf(x)));
}
__device__ __forceinline__ float sigmoid_tanh(float x){
    float t;
    asm("tanh.approx.f32 %0, %1;" : "=f"(t) : "f"(0.5f*x));
    return fmaf(0.5f, t, 0.5f);
}

// ---------------- E preconversion: float E -> packed half2 pairs ---------
__global__ void __launch_bounds__(256) kPrep(const float* __restrict__ E){
    int idx = blockIdx.x*256 + threadIdx.x;
    int atom = idx >> 8, o = idx & 255;
    if (o >= 252){ g_Eh[idx] = __float2half2_rn(0.f); return; }
    int r = o / 21, kp = o - r*21;
    size_t row = (size_t)atom*12 + r;
    float e0 = E[row*NBRF + kp*2];
    float e1 = (kp < 20) ? E[row*NBRF + kp*2 + 1] : 0.f;
    g_Eh[idx] = __floats2half2_rn(e0, e1);
}

// ---------------- embed: x = atom_fea @ W_embed + b ---------------------
__global__ void __launch_bounds__(256) kEmbed(const float* __restrict__ A,
                                              const float* __restrict__ W,
                                              const float* __restrict__ b){
    __shared__ float sW[ORIG*AF];
    __shared__ float sb_[AF];
    __shared__ float sIn[8][4*ORIG];
    int tid = threadIdx.x;
    for (int i = tid; i < ORIG*AF; i += 256) sW[i] = W[i];
    if (tid < AF) sb_[tid] = b[tid];
    __syncthreads();
    int warp = tid >> 5, lane = tid & 31;
    int gw = blockIdx.x*8 + warp, nw = gridDim.x*8;
    float b0 = sb_[lane*2], b1 = sb_[lane*2+1];
    for (int grp = gw; grp < N_ATOMSC/4; grp += nw){
        int base = grp*4;
        for (int i = lane; i < 4*ORIG; i += 32)
            sIn[warp][i] = A[base*ORIG + i];
        __syncwarp();
        float acc[4][2];
        #pragma unroll
        for (int r = 0; r < 4; r++){ acc[r][0] = b0; acc[r][1] = b1; }
        #pragma unroll 4
        for (int k = 0; k < ORIG; k++){
            float2 w = *(const float2*)&sW[k*AF + lane*2];
            #pragma unroll
            for (int r = 0; r < 4; r++){
                float xv = sIn[warp][r*ORIG + k];
                acc[r][0] = fmaf(xv, w.x, acc[r][0]);
                acc[r][1] = fmaf(xv, w.y, acc[r][1]);
            }
        }
        #pragma unroll
        for (int r = 0; r < 4; r++)
            *(float2*)&g_x[(base+r)*AF + lane*2] = make_float2(acc[r][0], acc[r][1]);
        __syncwarp();
    }
}

// ---------------- P/Q GEMM core (HFMA2, dual parity chains) --------------
__device__ __forceinline__ void pq_gemm_body(const uint4* sWq, const __half2* sXw,
                                             int base){
    __half2 z = __float2half2_rn(0.f);
    __half2 aA[2][4] = {{z,z,z,z},{z,z,z,z}};
    __half2 aB[2][4] = {{z,z,z,z},{z,z,z,z}};
    int lane = threadIdx.x & 31;
    #pragma unroll 4
    for (int kp = 0; kp < 32; kp++){
        uint4 wAu = sWq[(2*kp)*32 + lane];
        uint4 wBu = sWq[(2*kp+1)*32 + lane];
        __half2 wA[4] = {*(__half2*)&wAu.x, *(__half2*)&wAu.y,
                         *(__half2*)&wAu.z, *(__half2*)&wAu.w};
        __half2 wB[4] = {*(__half2*)&wBu.x, *(__half2*)&wBu.y,
                         *(__half2*)&wBu.z, *(__half2*)&wBu.w};
        #pragma unroll
        for (int a = 0; a < 2; a++){
            __half2 ep = sXw[a*33 + kp];
            __half2 eA = __low2half2(ep), eB = __high2half2(ep);
            #pragma unroll
            for (int c = 0; c < 4; c++){
                aA[a][c] = __hfma2(eA, wA[c], aA[a][c]);
                aB[a][c] = __hfma2(eB, wB[c], aB[a][c]);
            }
        }
    }
    #pragma unroll
    for (int a = 0; a < 2; a++){
        float2 f[4];
        #pragma unroll
        for (int c = 0; c < 4; c++)
            f[c] = __half22float2(__hadd2(aA[a][c], aB[a][c]));
        float* dst = (lane < 16) ? &g_P[(size_t)(base+a)*G1 + lane*8]
                                 : &g_Q[(size_t)(base+a)*G1 + (lane-16)*8];
        *(float4*)dst       = make_float4(f[0].x, f[0].y, f[1].x, f[1].y);
        *(float4*)(dst + 4) = make_float4(f[2].x, f[2].y, f[3].x, f[3].y);
    }
}

__device__ __forceinline__ void load_pq_weights(uint4* sWq, const float* Wf){
    __half2* sWh = (__half2*)sWq;
    int tid = threadIdx.x;
    for (int i = tid; i < 64*128; i += 256){
        int k = i >> 7, cp = i & 127;
        int c0 = cp*2, c1 = cp*2 + 1;
        float w0 = (c0 < G1) ? Wf[k*G1 + c0] : Wf[(AF + k)*G1 + (c0 - G1)];
        float w1 = (c1 < G1) ? Wf[k*G1 + c1] : Wf[(AF + k)*G1 + (c1 - G1)];
        sWh[k*128 + cp] = __floats2half2_rn(w0, w1);
    }
}

// ---------------- standalone P/Q GEMM (layer 0) ---------------------------
__global__ void __launch_bounds__(256) kPQ2(const float* __restrict__ Wf){
    __shared__ uint4 sWq[64*32];
    __shared__ __half2 sX[8][2*33];
    int tid = threadIdx.x, wid = tid >> 5, lane = tid & 31;
    load_pq_weights(sWq, Wf);
    __syncthreads();
    int gw = blockIdx.x*8 + wid, nw = gridDim.x*8;
    for (int grp = gw; grp < N_ATOMSC/2; grp += nw){
        int base = grp*2;
        for (int i = lane; i < 64; i += 32){
            int a = i >> 5, kp = i & 31;
            sX[wid][a*33 + kp] = __floats2half2_rn(g_x[(base+a)*AF + kp*2],
                                                   g_x[(base+a)*AF + kp*2 + 1]);
        }
        __syncwarp();
        pq_gemm_body(sWq, sX[wid], base);
        __syncwarp();
    }
}

// ---------------- fused residual update + next-layer P/Q GEMM ------------
__global__ void __launch_bounds__(256) kUpdatePQ(const float* __restrict__ WfNext){
    __shared__ uint4 sWq[64*32];
    __shared__ __half2 sX[8][2*33];
    int tid = threadIdx.x, wid = tid >> 5, lane = tid & 31;
    load_pq_weights(sWq, WfNext);
    __syncthreads();
    int gw = blockIdx.x*8 + wid, nw = gridDim.x*8;
    for (int grp = gw; grp < N_ATOMSC/2; grp += nw){
        int base = grp*2;
        for (int i = lane; i < 64; i += 32){
            int a = i >> 5, kp = i & 31;
            size_t off = (size_t)(base+a)*AF + kp*2;
            float2 xv = *(const float2*)&g_x[off];
            float2 nv = *(const float2*)&g_ns[off];
            float2 a2 = *(const float2*)&g_a2[kp*2];
            float2 b2 = *(const float2*)&g_b2[kp*2];
            float x0 = softplus_fast(xv.x + fmaf(nv.x, a2.x, b2.x));
            float x1 = softplus_fast(xv.y + fmaf(nv.y, a2.y, b2.y));
            *(float2*)&g_x[off] = make_float2(x0, x1);
            sX[wid][a*33 + kp] = __floats2half2_rn(x0, x1);
        }
        __syncwarp();
        pq_gemm_body(sWq, sX[wid], base);
        __syncwarp();
    }
}

// ---------------- edge kernel: 12 rows/warp, dual chains (R11 config) ----
__global__ void __launch_bounds__(256, 2) kEdgeH(const int*   __restrict__ NI,
                                                 const float* __restrict__ Wf,
                                                 const float* __restrict__ bf){
    __shared__ uint2 sWq[42*32];                  // 10752 B
    __shared__ float sb[G1], sS[G1], sQ[G1];
    __shared__ __align__(16) __half2 sE[8][256];  // 8192 B (64 uint4 per warp)
    int tid = threadIdx.x, wid = tid >> 5, lane = tid & 31;
    const float* WfE = Wf + 128*G1;
    __half2* sWh = (__half2*)sWq;
    for (int i = tid; i < NBRF*64; i += 256){
        int k = i >> 6, cp = i & 63;
        sWh[k*64 + cp] = __floats2half2_rn(WfE[k*G1 + cp*2], WfE[k*G1 + cp*2 + 1]);
    }
    for (int i = NBRF*64 + tid; i < 42*64; i += 256) sWh[i] = __float2half2_rn(0.f);
    if (tid < G1){ sb[tid] = bf[tid]; sS[tid] = 0.f; sQ[tid] = 0.f; }
    __syncthreads();

    float4 bb = *(const float4*)&sb[lane*4];
    float cs[4] = {0,0,0,0}, cq[4] = {0,0,0,0};

    const uint4* Eh4 = (const uint4*)g_Eh;        // 64 uint4 per atom
    int gw = blockIdx.x*8 + wid, nw = gridDim.x*8;
    uint4 er0, er1;
    if (gw < N_ATOMSC){
        er0 = Eh4[(size_t)gw*64 + lane];
        er1 = Eh4[(size_t)gw*64 + 32 + lane];
    }

    for (int n = gw; n < N_ATOMSC; n += nw){
        ((uint4*)sE[wid])[lane]      = er0;
        ((uint4*)sE[wid])[lane + 32] = er1;
        __syncwarp();
        int nn = n + nw;
        if (nn < N_ATOMSC){
            er0 = Eh4[(size_t)nn*64 + lane];
            er1 = Eh4[(size_t)nn*64 + 32 + lane];
        }

        size_t rb = (size_t)n * 12;
        int4 j0 = *(const int4*)&NI[rb];
        int4 j1 = *(const int4*)&NI[rb + 4];
        int4 j2 = *(const int4*)&NI[rb + 8];
        int jj[12] = {j0.x,j0.y,j0.z,j0.w, j1.x,j1.y,j1.z,j1.w, j2.x,j2.y,j2.z,j2.w};
        float4 p = *(const float4*)&g_P[(size_t)n*G1 + lane*4];
        float4 pqb = make_float4(p.x + bb.x, p.y + bb.y, p.z + bb.z, p.w + bb.w);

        __half2 z = __float2half2_rn(0.f);
        __half2 aA[12][2], aB[12][2];
        #pragma unroll
        for (int r = 0; r < 12; r++){
            aA[r][0] = z; aA[r][1] = z; aB[r][0] = z; aB[r][1] = z;
        }
        #pragma unroll 3
        for (int kp = 0; kp < 21; kp++){
            uint2 wAu = sWq[(2*kp)*32 + lane];
            uint2 wBu = sWq[(2*kp+1)*32 + lane];
            __half2 wA0 = *(__half2*)&wAu.x, wA1 = *(__half2*)&wAu.y;
            __half2 wB0 = *(__half2*)&wBu.x, wB1 = *(__half2*)&wBu.y;
            #pragma unroll
            for (int r = 0; r < 12; r++){
                __half2 ep = sE[wid][r*21 + kp];
                __half2 eA = __low2half2(ep), eB = __high2half2(ep);
                aA[r][0] = __hfma2(eA, wA0, aA[r][0]);
                aA[r][1] = __hfma2(eA, wA1, aA[r][1]);
                aB[r][0] = __hfma2(eB, wB0, aB[r][0]);
                aB[r][1] = __hfma2(eB, wB1, aB[r][1]);
            }
        }
        #pragma unroll
        for (int r = 0; r < 12; r++){
            float4 q = *(const float4*)&g_Q[(size_t)jj[r]*G1 + lane*4];
            float2 f0 = __half22float2(__hadd2(aA[r][0], aB[r][0]));
            float2 f1 = __half22float2(__hadd2(aA[r][1], aB[r][1]));
            float v0 = f0.x + pqb.x + q.x;
            float v1 = f0.y + pqb.y + q.y;
            float v2 = f1.x + pqb.z + q.z;
            float v3 = f1.y + pqb.w + q.w;
            cs[0] += v0; cq[0] = fmaf(v0, v0, cq[0]);
            cs[1] += v1; cq[1] = fmaf(v1, v1, cq[1]);
            cs[2] += v2; cq[2] = fmaf(v2, v2, cq[2]);
            cs[3] += v3; cq[3] = fmaf(v3, v3, cq[3]);
            __half2 h0 = __floats2half2_rn(v0, v1);
            __half2 h1 = __floats2half2_rn(v2, v3);
            *(uint2*)&g_gated[(rb + r)*(G1/2) + lane*2] =
                make_uint2(*(unsigned*)&h0, *(unsigned*)&h1);
        }
        __syncwarp();
    }
    atomicAdd(&sS[lane*4+0], cs[0]); atomicAdd(&sQ[lane*4+0], cq[0]);
    atomicAdd(&sS[lane*4+1], cs[1]); atomicAdd(&sQ[lane*4+1], cq[1]);
    atomicAdd(&sS[lane*4+2], cs[2]); atomicAdd(&sQ[lane*4+2], cq[2]);
    atomicAdd(&sS[lane*4+3], cs[3]); atomicAdd(&sQ[lane*4+3], cq[3]);
    __syncthreads();
    if (tid < G1){
        atomicAdd(&g_s1[tid],  sS[tid]);
        atomicAdd(&g_ss1[tid], sQ[tid]);
    }
}

// ---------------- BN1 finalize -------------------------------------------
__global__ void kBN1(const float* __restrict__ gam, const float* __restrict__ bet){
    int f = threadIdx.x;
    float inv = 1.f / (float)NM;
    float m = g_s1[f]*inv;
    float v = g_ss1[f]*inv - m*m;
    float a = gam[f] * rsqrtf(v + EPSL);
    g_a1[f] = a;
    g_b1[f] = bet[f] - m*a;
    g_s1[f] = 0.f; g_ss1[f] = 0.f;
}

// ---------------- reduce: preloaded MLP, sigmoid*softplus -----------------
__global__ void __launch_bounds__(256) kReduce(){
    __shared__ float rs[AF], rq[AF];
    int tid = threadIdx.x;
    int wid = tid >> 5, lane = tid & 31;
    if (tid < AF){ rs[tid] = 0.f; rq[tid] = 0.f; }
    __syncthreads();
    int f2 = lane*2;
    float A1x = g_a1[f2],    A1y = g_a1[f2+1];
    float B1x = g_b1[f2],    B1y = g_b1[f2+1];
    float A2x = g_a1[64+f2], A2y = g_a1[64+f2+1];
    float B2x = g_b1[64+f2], B2y = g_b1[64+f2+1];
    float s0=0,s1=0,q0=0,q1=0;
    int gw = blockIdx.x*8 + wid, nw = gridDim.x*8;
    for (int n = gw; n < N_ATOMSC; n += nw){
        const __half2* bh = g_gated + (size_t)n*(M_NBR*(G1/2)) + lane;
        // preload all 24 half2 first (guaranteed MLP=24)
        __half2 hf[M_NBR], hc[M_NBR];
        #pragma unroll
        for (int m = 0; m < M_NBR; m++){
            hf[m] = bh[m*64];
            hc[m] = bh[m*64 + 32];
        }
        float a0 = 0.f, a1 = 0.f;
        #pragma unroll
        for (int m = 0; m < M_NBR; m++){
            float2 zf = __half22float2(hf[m]);
            float2 zc = __half22float2(hc[m]);
            float xf0 = fmaf(zf.x, A1x, B1x);
            float xf1 = fmaf(zf.y, A1y, B1y);
            float xc0 = fmaf(zc.x, A2x, B2x);
            float xc1 = fmaf(zc.y, A2y, B2y);
            float sg0 = sigmoid_tanh(xf0);
            float sg1 = sigmoid_tanh(xf1);
            a0 = fmaf(sg0, softplus_fast(xc0), a0);
            a1 = fmaf(sg1, softplus_fast(xc1), a1);
        }
        *(float2*)&g_ns[(size_t)n*AF + f2] = make_float2(a0, a1);
        s0 += a0; q0 = fmaf(a0, a0, q0);
        s1 += a1; q1 = fmaf(a1, a1, q1);
    }
    atomicAdd(&rs[f2],   s0); atomicAdd(&rq[f2],   q0);
    atomicAdd(&rs[f2+1], s1); atomicAdd(&rq[f2+1], q1);
    __syncthreads();
    if (tid < AF){
        atomicAdd(&g_s2[tid],  rs[tid]);
        atomicAdd(&g_ss2[tid], rq[tid]);
    }
}

// ---------------- BN2 finalize ------------------------------------------
__global__ void kBN2(const float* __restrict__ gam, const float* __restrict__ bet){
    int f = threadIdx.x;
    float inv = 1.f / (float)N_ATOMSC;
    float m = g_s2[f]*inv;
    float v = g_ss2[f]*inv - m*m;
    float a = gam[f] * rsqrtf(v + EPSL);
    g_a2[f] = a;
    g_b2[f] = bet[f] - m*a;
    g_s2[f] = 0.f; g_ss2[f] = 0.f;
}

// ---------------- plain residual update (last layer) ---------------------
__global__ void __launch_bounds__(256) kUpdate(){
    int i4 = blockIdx.x*256 + threadIdx.x;
    int f = (i4 & 15) * 4;
    float4 xv = *(const float4*)&g_x[i4*4];
    float4 nv = *(const float4*)&g_ns[i4*4];
    float4 a2 = *(const float4*)&g_a2[f];
    float4 b2 = *(const float4*)&g_b2[f];
    float4 o;
    o.x = softplus_fast(xv.x + fmaf(nv.x, a2.x, b2.x));
    o.y = softplus_fast(xv.y + fmaf(nv.y, a2.y, b2.y));
    o.z = softplus_fast(xv.z + fmaf(nv.z, a2.z, b2.z));
    o.w = softplus_fast(xv.w + fmaf(nv.w, a2.w, b2.w));
    *(float4*)&g_x[i4*4] = o;
}

// ---------------- pool + FC + ReLU ---------------------------------------
__global__ void __launch_bounds__(128) kPool(const int* __restrict__ cidx,
                                             const float* __restrict__ Wp,
                                             const float* __restrict__ bp,
                                             float* __restrict__ out){
    __shared__ float sm[AF];
    int c = blockIdx.x, tid = threadIdx.x;
    if (tid < AF){
        float s = 0.f;
        #pragma unroll 5
        for (int a = 0; a < APC; a++){
            int idx = cidx[c*APC + a];
            s += g_x[idx*AF + tid];
        }
        sm[tid] = s * (1.f/(float)APC);
    }
    __syncthreads();
    float acc = bp[tid];
    #pragma unroll 8
    for (int k = 0; k < AF; k++)
        acc = fmaf(sm[k], Wp[k*OUTD + tid], acc);
    out[c*OUTD + tid] = fmaxf(acc, 0.f);
}

// ---------------- launcher ------------------------------------------------
extern "C" void kernel_launch(void* const* d_in, const int* in_sizes, int n_in,
                              void* d_out, int out_size){
    const float* atom_fea = (const float*)d_in[0];
    const float* nbr_fea  = (const float*)d_in[1];
    const int*   nbr_idx  = (const int*)  d_in[2];
    const int*   cidx     = (const int*)  d_in[3];
    const float* W_embed  = (const float*)d_in[4];
    const float* b_embed  = (const float*)d_in[5];
    const float* W_full   = (const float*)d_in[6];
    const float* b_full   = (const float*)d_in[7];
    const float* g1       = (const float*)d_in[8];
    const float* be1      = (const float*)d_in[9];
    const float* g2       = (const float*)d_in[10];
    const float* be2      = (const float*)d_in[11];
    const float* Wp       = (const float*)d_in[12];
    const float* bp       = (const float*)d_in[13];
    float* out = (float*)d_out;

    kEmbed<<<512, 256>>>(atom_fea, W_embed, b_embed);        // launch 0
    kPrep <<<N_ATOMSC, 256>>>(nbr_fea);                      // launch 1
    kPQ2  <<<592, 256>>>(W_full);                            // launch 2
    for (int l = 0; l < 3; l++){
        const float* Wf = W_full + (size_t)l * 169 * G1;
        kEdgeH <<<296, 256>>>(nbr_idx, Wf, b_full + l*G1);   // l==0 -> launch 3
        kBN1   <<<1, 128>>>(g1 + l*G1, be1 + l*G1);
        kReduce<<<1568, 256>>>();
        kBN2   <<<1, 64>>>(g2 + l*AF, be2 + l*AF);
        if (l < 2){
            const float* WfN = W_full + (size_t)(l+1) * 169 * G1;
            kUpdatePQ<<<592, 256>>>(WfN);
        } else {
            kUpdate<<<(N_ATOMSC*AF/4)/256, 256>>>();
        }
    }
    kPool<<<NCRY, 128>>>(cidx, Wp, bp, out);
}

// round 14
// speedup vs baseline: 1.1517x; 1.0285x over previous
#include <cuda_runtime.h>
#include <cuda_fp16.h>
#include <math.h>
#include <stdint.h>

#define N_ATOMSC 100000
#define M_NBR    12
#define ORIG     92
#define NBRF     41
#define AF       64
#define G1       128
#define NM       (N_ATOMSC*M_NBR)
#define OUTD     128
#define NCRY     2000
#define APC      50
#define EPSL     1e-5f

#define EMB_BLKS 512

// ---------------- device scratch ----------------------------------------
__device__ float   g_x[N_ATOMSC*AF];
__device__ float   g_P[N_ATOMSC*G1];
__device__ float   g_Q[N_ATOMSC*G1];
__device__ __half2 g_gated[(size_t)NM*(G1/2)];       // fp16 gated (307 MB)
__device__ __align__(16) __half2 g_Eh[(size_t)N_ATOMSC*256];  // packed E pairs (102 MB)
__device__ float   g_ns[N_ATOMSC*AF];
__device__ float   g_s1[G1], g_ss1[G1];
__device__ float   g_s2[AF], g_ss2[AF], g_a2[AF], g_b2[AF];

__device__ __forceinline__ float softplus_fast(float x){
    return fmaxf(x, 0.f) + __logf(1.f + __expf(-fabsf(x)));
}
__device__ __forceinline__ float sigmoid_tanh(float x){
    float t;
    asm("tanh.approx.f32 %0, %1;" : "=f"(t) : "f"(0.5f*x));
    return fmaf(0.5f, t, 0.5f);
}

// ---------------- fused embed + E preconversion --------------------------
// blocks [0, EMB_BLKS): x = atom_fea @ W_embed + b
// blocks [EMB_BLKS, EMB_BLKS+100000): pack E floats -> half2 pairs
__global__ void __launch_bounds__(256) kEmbedPrep(const float* __restrict__ A,
                                                  const float* __restrict__ W,
                                                  const float* __restrict__ b,
                                                  const float* __restrict__ E){
    __shared__ float sW[ORIG*AF];
    __shared__ float sb_[AF];
    __shared__ float sIn[8][4*ORIG];
    int tid = threadIdx.x;
    if (blockIdx.x >= EMB_BLKS){
        int idx = (blockIdx.x - EMB_BLKS)*256 + tid;
        int o = idx & 255;
        if (o >= 252){ g_Eh[idx] = __float2half2_rn(0.f); return; }
        int atom = idx >> 8;
        int r = o / 21, kp = o - r*21;
        size_t row = (size_t)atom*12 + r;
        float e0 = E[row*NBRF + kp*2];
        float e1 = (kp < 20) ? E[row*NBRF + kp*2 + 1] : 0.f;
        g_Eh[idx] = __floats2half2_rn(e0, e1);
        return;
    }
    for (int i = tid; i < ORIG*AF; i += 256) sW[i] = W[i];
    if (tid < AF) sb_[tid] = b[tid];
    __syncthreads();
    int warp = tid >> 5, lane = tid & 31;
    int gw = blockIdx.x*8 + warp, nw = EMB_BLKS*8;
    float b0 = sb_[lane*2], b1 = sb_[lane*2+1];
    for (int grp = gw; grp < N_ATOMSC/4; grp += nw){
        int base = grp*4;
        for (int i = lane; i < 4*ORIG; i += 32)
            sIn[warp][i] = A[base*ORIG + i];
        __syncwarp();
        float acc[4][2];
        #pragma unroll
        for (int r = 0; r < 4; r++){ acc[r][0] = b0; acc[r][1] = b1; }
        #pragma unroll 4
        for (int k = 0; k < ORIG; k++){
            float2 w = *(const float2*)&sW[k*AF + lane*2];
            #pragma unroll
            for (int r = 0; r < 4; r++){
                float xv = sIn[warp][r*ORIG + k];
                acc[r][0] = fmaf(xv, w.x, acc[r][0]);
                acc[r][1] = fmaf(xv, w.y, acc[r][1]);
            }
        }
        #pragma unroll
        for (int r = 0; r < 4; r++)
            *(float2*)&g_x[(base+r)*AF + lane*2] = make_float2(acc[r][0], acc[r][1]);
        __syncwarp();
    }
}

// ---------------- P/Q GEMM core (HFMA2, dual parity chains) --------------
__device__ __forceinline__ void pq_gemm_body(const uint4* sWq, const __half2* sXw,
                                             int base){
    __half2 z = __float2half2_rn(0.f);
    __half2 aA[2][4] = {{z,z,z,z},{z,z,z,z}};
    __half2 aB[2][4] = {{z,z,z,z},{z,z,z,z}};
    int lane = threadIdx.x & 31;
    #pragma unroll 4
    for (int kp = 0; kp < 32; kp++){
        uint4 wAu = sWq[(2*kp)*32 + lane];
        uint4 wBu = sWq[(2*kp+1)*32 + lane];
        __half2 wA[4] = {*(__half2*)&wAu.x, *(__half2*)&wAu.y,
                         *(__half2*)&wAu.z, *(__half2*)&wAu.w};
        __half2 wB[4] = {*(__half2*)&wBu.x, *(__half2*)&wBu.y,
                         *(__half2*)&wBu.z, *(__half2*)&wBu.w};
        #pragma unroll
        for (int a = 0; a < 2; a++){
            __half2 ep = sXw[a*33 + kp];
            __half2 eA = __low2half2(ep), eB = __high2half2(ep);
            #pragma unroll
            for (int c = 0; c < 4; c++){
                aA[a][c] = __hfma2(eA, wA[c], aA[a][c]);
                aB[a][c] = __hfma2(eB, wB[c], aB[a][c]);
            }
        }
    }
    #pragma unroll
    for (int a = 0; a < 2; a++){
        float2 f[4];
        #pragma unroll
        for (int c = 0; c < 4; c++)
            f[c] = __half22float2(__hadd2(aA[a][c], aB[a][c]));
        float* dst = (lane < 16) ? &g_P[(size_t)(base+a)*G1 + lane*8]
                                 : &g_Q[(size_t)(base+a)*G1 + (lane-16)*8];
        *(float4*)dst       = make_float4(f[0].x, f[0].y, f[1].x, f[1].y);
        *(float4*)(dst + 4) = make_float4(f[2].x, f[2].y, f[3].x, f[3].y);
    }
}

__device__ __forceinline__ void load_pq_weights(uint4* sWq, const float* Wf){
    __half2* sWh = (__half2*)sWq;
    int tid = threadIdx.x;
    for (int i = tid; i < 64*128; i += 256){
        int k = i >> 7, cp = i & 127;
        int c0 = cp*2, c1 = cp*2 + 1;
        float w0 = (c0 < G1) ? Wf[k*G1 + c0] : Wf[(AF + k)*G1 + (c0 - G1)];
        float w1 = (c1 < G1) ? Wf[k*G1 + c1] : Wf[(AF + k)*G1 + (c1 - G1)];
        sWh[k*128 + cp] = __floats2half2_rn(w0, w1);
    }
}

// ---------------- standalone P/Q GEMM (layer 0) ---------------------------
__global__ void __launch_bounds__(256) kPQ2(const float* __restrict__ Wf){
    __shared__ uint4 sWq[64*32];
    __shared__ __half2 sX[8][2*33];
    int tid = threadIdx.x, wid = tid >> 5, lane = tid & 31;
    load_pq_weights(sWq, Wf);
    __syncthreads();
    int gw = blockIdx.x*8 + wid, nw = gridDim.x*8;
    for (int grp = gw; grp < N_ATOMSC/2; grp += nw){
        int base = grp*2;
        for (int i = lane; i < 64; i += 32){
            int a = i >> 5, kp = i & 31;
            sX[wid][a*33 + kp] = __floats2half2_rn(g_x[(base+a)*AF + kp*2],
                                                   g_x[(base+a)*AF + kp*2 + 1]);
        }
        __syncwarp();
        pq_gemm_body(sWq, sX[wid], base);
        __syncwarp();
    }
}

// ---------------- fused residual update + next-layer P/Q GEMM ------------
__global__ void __launch_bounds__(256) kUpdatePQ(const float* __restrict__ WfNext){
    __shared__ uint4 sWq[64*32];
    __shared__ __half2 sX[8][2*33];
    int tid = threadIdx.x, wid = tid >> 5, lane = tid & 31;
    load_pq_weights(sWq, WfNext);
    __syncthreads();
    int gw = blockIdx.x*8 + wid, nw = gridDim.x*8;
    for (int grp = gw; grp < N_ATOMSC/2; grp += nw){
        int base = grp*2;
        for (int i = lane; i < 64; i += 32){
            int a = i >> 5, kp = i & 31;
            size_t off = (size_t)(base+a)*AF + kp*2;
            float2 xv = *(const float2*)&g_x[off];
            float2 nv = *(const float2*)&g_ns[off];
            float2 a2 = *(const float2*)&g_a2[kp*2];
            float2 b2 = *(const float2*)&g_b2[kp*2];
            float x0 = softplus_fast(xv.x + fmaf(nv.x, a2.x, b2.x));
            float x1 = softplus_fast(xv.y + fmaf(nv.y, a2.y, b2.y));
            *(float2*)&g_x[off] = make_float2(x0, x1);
            sX[wid][a*33 + kp] = __floats2half2_rn(x0, x1);
        }
        __syncwarp();
        pq_gemm_body(sWq, sX[wid], base);
        __syncwarp();
    }
}

// ---------------- edge kernel: 12 rows/warp, dual chains (R11 config) ----
__global__ void __launch_bounds__(256, 2) kEdgeH(const int*   __restrict__ NI,
                                                 const float* __restrict__ Wf,
                                                 const float* __restrict__ bf){
    __shared__ uint2 sWq[42*32];                  // 10752 B
    __shared__ float sb[G1], sS[G1], sQ[G1];
    __shared__ __align__(16) __half2 sE[8][256];  // 8192 B
    int tid = threadIdx.x, wid = tid >> 5, lane = tid & 31;
    const float* WfE = Wf + 128*G1;
    __half2* sWh = (__half2*)sWq;
    for (int i = tid; i < NBRF*64; i += 256){
        int k = i >> 6, cp = i & 63;
        sWh[k*64 + cp] = __floats2half2_rn(WfE[k*G1 + cp*2], WfE[k*G1 + cp*2 + 1]);
    }
    for (int i = NBRF*64 + tid; i < 42*64; i += 256) sWh[i] = __float2half2_rn(0.f);
    if (tid < G1){ sb[tid] = bf[tid]; sS[tid] = 0.f; sQ[tid] = 0.f; }
    __syncthreads();

    float4 bb = *(const float4*)&sb[lane*4];
    float cs[4] = {0,0,0,0}, cq[4] = {0,0,0,0};

    const uint4* Eh4 = (const uint4*)g_Eh;
    int gw = blockIdx.x*8 + wid, nw = gridDim.x*8;
    uint4 er0, er1;
    if (gw < N_ATOMSC){
        er0 = Eh4[(size_t)gw*64 + lane];
        er1 = Eh4[(size_t)gw*64 + 32 + lane];
    }

    for (int n = gw; n < N_ATOMSC; n += nw){
        ((uint4*)sE[wid])[lane]      = er0;
        ((uint4*)sE[wid])[lane + 32] = er1;
        __syncwarp();
        int nn = n + nw;
        if (nn < N_ATOMSC){
            er0 = Eh4[(size_t)nn*64 + lane];
            er1 = Eh4[(size_t)nn*64 + 32 + lane];
        }

        size_t rb = (size_t)n * 12;
        int4 j0 = *(const int4*)&NI[rb];
        int4 j1 = *(const int4*)&NI[rb + 4];
        int4 j2 = *(const int4*)&NI[rb + 8];
        int jj[12] = {j0.x,j0.y,j0.z,j0.w, j1.x,j1.y,j1.z,j1.w, j2.x,j2.y,j2.z,j2.w};
        float4 p = *(const float4*)&g_P[(size_t)n*G1 + lane*4];
        float4 pqb = make_float4(p.x + bb.x, p.y + bb.y, p.z + bb.z, p.w + bb.w);

        __half2 z = __float2half2_rn(0.f);
        __half2 aA[12][2], aB[12][2];
        #pragma unroll
        for (int r = 0; r < 12; r++){
            aA[r][0] = z; aA[r][1] = z; aB[r][0] = z; aB[r][1] = z;
        }
        #pragma unroll 3
        for (int kp = 0; kp < 21; kp++){
            uint2 wAu = sWq[(2*kp)*32 + lane];
            uint2 wBu = sWq[(2*kp+1)*32 + lane];
            __half2 wA0 = *(__half2*)&wAu.x, wA1 = *(__half2*)&wAu.y;
            __half2 wB0 = *(__half2*)&wBu.x, wB1 = *(__half2*)&wBu.y;
            #pragma unroll
            for (int r = 0; r < 12; r++){
                __half2 ep = sE[wid][r*21 + kp];
                __half2 eA = __low2half2(ep), eB = __high2half2(ep);
                aA[r][0] = __hfma2(eA, wA0, aA[r][0]);
                aA[r][1] = __hfma2(eA, wA1, aA[r][1]);
                aB[r][0] = __hfma2(eB, wB0, aB[r][0]);
                aB[r][1] = __hfma2(eB, wB1, aB[r][1]);
            }
        }
        #pragma unroll
        for (int r = 0; r < 12; r++){
            float4 q = *(const float4*)&g_Q[(size_t)jj[r]*G1 + lane*4];
            float2 f0 = __half22float2(__hadd2(aA[r][0], aB[r][0]));
            float2 f1 = __half22float2(__hadd2(aA[r][1], aB[r][1]));
            float v0 = f0.x + pqb.x + q.x;
            float v1 = f0.y + pqb.y + q.y;
            float v2 = f1.x + pqb.z + q.z;
            float v3 = f1.y + pqb.w + q.w;
            cs[0] += v0; cq[0] = fmaf(v0, v0, cq[0]);
            cs[1] += v1; cq[1] = fmaf(v1, v1, cq[1]);
            cs[2] += v2; cq[2] = fmaf(v2, v2, cq[2]);
            cs[3] += v3; cq[3] = fmaf(v3, v3, cq[3]);
            __half2 h0 = __floats2half2_rn(v0, v1);
            __half2 h1 = __floats2half2_rn(v2, v3);
            *(uint2*)&g_gated[(rb + r)*(G1/2) + lane*2] =
                make_uint2(*(unsigned*)&h0, *(unsigned*)&h1);
        }
        __syncwarp();
    }
    atomicAdd(&sS[lane*4+0], cs[0]); atomicAdd(&sQ[lane*4+0], cq[0]);
    atomicAdd(&sS[lane*4+1], cs[1]); atomicAdd(&sQ[lane*4+1], cq[1]);
    atomicAdd(&sS[lane*4+2], cs[2]); atomicAdd(&sQ[lane*4+2], cq[2]);
    atomicAdd(&sS[lane*4+3], cs[3]); atomicAdd(&sQ[lane*4+3], cq[3]);
    __syncthreads();
    if (tid < G1){
        atomicAdd(&g_s1[tid],  sS[tid]);
        atomicAdd(&g_ss1[tid], sQ[tid]);
    }
}

// ---------------- reduce: inline BN1 fold + sigmoid*softplus --------------
__global__ void __launch_bounds__(256) kReduce(const float* __restrict__ gam1,
                                               const float* __restrict__ bet1){
    __shared__ float rs[AF], rq[AF];
    int tid = threadIdx.x;
    int wid = tid >> 5, lane = tid & 31;
    if (tid < AF){ rs[tid] = 0.f; rq[tid] = 0.f; }
    int f2 = lane*2;
    // fold BN1 coefficients locally (redundant per thread, trivially cheap)
    float A1x, A1y, B1x, B1y, A2x, A2y, B2x, B2y;
    {
        const float inv = 1.f / (float)NM;
        #pragma unroll
        for (int t = 0; t < 4; t++){
            int f = (t >> 1) ? (64 + f2 + (t & 1)) : (f2 + (t & 1));
            float m = g_s1[f]*inv;
            float v = g_ss1[f]*inv - m*m;
            float a = gam1[f] * rsqrtf(v + EPSL);
            float bb = bet1[f] - m*a;
            if (t == 0){ A1x = a; B1x = bb; }
            else if (t == 1){ A1y = a; B1y = bb; }
            else if (t == 2){ A2x = a; B2x = bb; }
            else { A2y = a; B2y = bb; }
        }
    }
    __syncthreads();
    float s0=0,s1=0,q0=0,q1=0;
    int gw = blockIdx.x*8 + wid, nw = gridDim.x*8;
    for (int n = gw; n < N_ATOMSC; n += nw){
        const __half2* bh = g_gated + (size_t)n*(M_NBR*(G1/2)) + lane;
        __half2 hf[M_NBR], hc[M_NBR];
        #pragma unroll
        for (int m = 0; m < M_NBR; m++){
            hf[m] = bh[m*64];
            hc[m] = bh[m*64 + 32];
        }
        float a0 = 0.f, a1 = 0.f;
        #pragma unroll
        for (int m = 0; m < M_NBR; m++){
            float2 zf = __half22float2(hf[m]);
            float2 zc = __half22float2(hc[m]);
            float xf0 = fmaf(zf.x, A1x, B1x);
            float xf1 = fmaf(zf.y, A1y, B1y);
            float xc0 = fmaf(zc.x, A2x, B2x);
            float xc1 = fmaf(zc.y, A2y, B2y);
            float sg0 = sigmoid_tanh(xf0);
            float sg1 = sigmoid_tanh(xf1);
            a0 = fmaf(sg0, softplus_fast(xc0), a0);
            a1 = fmaf(sg1, softplus_fast(xc1), a1);
        }
        *(float2*)&g_ns[(size_t)n*AF + f2] = make_float2(a0, a1);
        s0 += a0; q0 = fmaf(a0, a0, q0);
        s1 += a1; q1 = fmaf(a1, a1, q1);
    }
    atomicAdd(&rs[f2],   s0); atomicAdd(&rq[f2],   q0);
    atomicAdd(&rs[f2+1], s1); atomicAdd(&rq[f2+1], q1);
    __syncthreads();
    if (tid < AF){
        atomicAdd(&g_s2[tid],  rs[tid]);
        atomicAdd(&g_ss2[tid], rq[tid]);
    }
}

// ---------------- BN2 finalize + BN1 stat reset ---------------------------
__global__ void kBN2(const float* __restrict__ gam, const float* __restrict__ bet){
    int f = threadIdx.x;                 // 64 threads
    float inv = 1.f / (float)N_ATOMSC;
    float m = g_s2[f]*inv;
    float v = g_ss2[f]*inv - m*m;
    float a = gam[f] * rsqrtf(v + EPSL);
    g_a2[f] = a;
    g_b2[f] = bet[f] - m*a;
    g_s2[f] = 0.f; g_ss2[f] = 0.f;
    // reset BN1 stats for the next layer (runs after kReduce consumed them)
    g_s1[f] = 0.f;      g_ss1[f] = 0.f;
    g_s1[f+64] = 0.f;   g_ss1[f+64] = 0.f;
}

// ---------------- plain residual update (last layer) ---------------------
__global__ void __launch_bounds__(256) kUpdate(){
    int i4 = blockIdx.x*256 + threadIdx.x;
    int f = (i4 & 15) * 4;
    float4 xv = *(const float4*)&g_x[i4*4];
    float4 nv = *(const float4*)&g_ns[i4*4];
    float4 a2 = *(const float4*)&g_a2[f];
    float4 b2 = *(const float4*)&g_b2[f];
    float4 o;
    o.x = softplus_fast(xv.x + fmaf(nv.x, a2.x, b2.x));
    o.y = softplus_fast(xv.y + fmaf(nv.y, a2.y, b2.y));
    o.z = softplus_fast(xv.z + fmaf(nv.z, a2.z, b2.z));
    o.w = softplus_fast(xv.w + fmaf(nv.w, a2.w, b2.w));
    *(float4*)&g_x[i4*4] = o;
}

// ---------------- pool + FC + ReLU ---------------------------------------
__global__ void __launch_bounds__(128) kPool(const int* __restrict__ cidx,
                                             const float* __restrict__ Wp,
                                             const float* __restrict__ bp,
                                             float* __restrict__ out){
    __shared__ float sm[AF];
    int c = blockIdx.x, tid = threadIdx.x;
    if (tid < AF){
        float s = 0.f;
        #pragma unroll 5
        for (int a = 0; a < APC; a++){
            int idx = cidx[c*APC + a];
            s += g_x[idx*AF + tid];
        }
        sm[tid] = s * (1.f/(float)APC);
    }
    __syncthreads();
    float acc = bp[tid];
    #pragma unroll 8
    for (int k = 0; k < AF; k++)
        acc = fmaf(sm[k], Wp[k*OUTD + tid], acc);
    out[c*OUTD + tid] = fmaxf(acc, 0.f);
}

// ---------------- launcher ------------------------------------------------
extern "C" void kernel_launch(void* const* d_in, const int* in_sizes, int n_in,
                              void* d_out, int out_size){
    const float* atom_fea = (const float*)d_in[0];
    const float* nbr_fea  = (const float*)d_in[1];
    const int*   nbr_idx  = (const int*)  d_in[2];
    const int*   cidx     = (const int*)  d_in[3];
    const float* W_embed  = (const float*)d_in[4];
    const float* b_embed  = (const float*)d_in[5];
    const float* W_full   = (const float*)d_in[6];
    const float* b_full   = (const float*)d_in[7];
    const float* g1       = (const float*)d_in[8];
    const float* be1      = (const float*)d_in[9];
    const float* g2       = (const float*)d_in[10];
    const float* be2      = (const float*)d_in[11];
    const float* Wp       = (const float*)d_in[12];
    const float* bp       = (const float*)d_in[13];
    float* out = (float*)d_out;

    kEmbedPrep<<<EMB_BLKS + N_ATOMSC, 256>>>(atom_fea, W_embed, b_embed, nbr_fea); // 0
    kPQ2<<<592, 256>>>(W_full);                                                    // 1
    for (int l = 0; l < 3; l++){
        const float* Wf = W_full + (size_t)l * 169 * G1;
        kEdgeH <<<296, 256>>>(nbr_idx, Wf, b_full + l*G1);   // l==0 -> launch 2
        kReduce<<<1184, 256>>>(g1 + l*G1, be1 + l*G1);       // l==0 -> launch 3 (profiled)
        kBN2   <<<1, 64>>>(g2 + l*AF, be2 + l*AF);
        if (l < 2){
            const float* WfN = W_full + (size_t)(l+1) * 169 * G1;
            kUpdatePQ<<<592, 256>>>(WfN);
        } else {
            kUpdate<<<(N_ATOMSC*AF/4)/256, 256>>>();
        }
    }
    kPool<<<NCRY, 128>>>(cidx, Wp, bp, out);
}

// round 15
// speedup vs baseline: 1.1843x; 1.0283x over previous
#include <cuda_runtime.h>
#include <cuda_fp16.h>
#include <math.h>
#include <stdint.h>

#define N_ATOMSC 100000
#define M_NBR    12
#define ORIG     92
#define NBRF     41
#define AF       64
#define G1       128
#define NM       (N_ATOMSC*M_NBR)
#define OUTD     128
#define NCRY     2000
#define APC      50
#define EPSL     1e-5f

#define EMB_BLKS 512

// ---------------- device scratch ----------------------------------------
__device__ float   g_x[N_ATOMSC*AF];
__device__ float   g_P[N_ATOMSC*G1];
__device__ float   g_Q[N_ATOMSC*G1];
__device__ __half2 g_gated[(size_t)NM*(G1/2)];       // fp16 gated (307 MB)
__device__ __align__(16) __half2 g_Eh[(size_t)N_ATOMSC*256];  // packed E pairs (102 MB)
__device__ float   g_ns[N_ATOMSC*AF];
__device__ float   g_s1[G1], g_ss1[G1];
__device__ float   g_s2[AF], g_ss2[AF], g_a2[AF], g_b2[AF];

__device__ __forceinline__ float softplus_fast(float x){
    return fmaxf(x, 0.f) + __logf(1.f + __expf(-fabsf(x)));
}
__device__ __forceinline__ float sigmoid_tanh(float x){
    float t;
    asm("tanh.approx.f32 %0, %1;" : "=f"(t) : "f"(0.5f*x));
    return fmaf(0.5f, t, 0.5f);
}

// ---------------- fused embed + E preconversion --------------------------
__global__ void __launch_bounds__(256) kEmbedPrep(const float* __restrict__ A,
                                                  const float* __restrict__ W,
                                                  const float* __restrict__ b,
                                                  const float* __restrict__ E){
    __shared__ float sW[ORIG*AF];
    __shared__ float sb_[AF];
    __shared__ float sIn[8][4*ORIG];
    int tid = threadIdx.x;
    if (blockIdx.x >= EMB_BLKS){
        int idx = (blockIdx.x - EMB_BLKS)*256 + tid;
        int o = idx & 255;
        if (o >= 252){ g_Eh[idx] = __float2half2_rn(0.f); return; }
        int atom = idx >> 8;
        int r = o / 21, kp = o - r*21;
        size_t row = (size_t)atom*12 + r;
        float e0 = E[row*NBRF + kp*2];
        float e1 = (kp < 20) ? E[row*NBRF + kp*2 + 1] : 0.f;
        g_Eh[idx] = __floats2half2_rn(e0, e1);
        return;
    }
    for (int i = tid; i < ORIG*AF; i += 256) sW[i] = W[i];
    if (tid < AF) sb_[tid] = b[tid];
    __syncthreads();
    int warp = tid >> 5, lane = tid & 31;
    int gw = blockIdx.x*8 + warp, nw = EMB_BLKS*8;
    float b0 = sb_[lane*2], b1 = sb_[lane*2+1];
    for (int grp = gw; grp < N_ATOMSC/4; grp += nw){
        int base = grp*4;
        for (int i = lane; i < 4*ORIG; i += 32)
            sIn[warp][i] = A[base*ORIG + i];
        __syncwarp();
        float acc[4][2];
        #pragma unroll
        for (int r = 0; r < 4; r++){ acc[r][0] = b0; acc[r][1] = b1; }
        #pragma unroll 4
        for (int k = 0; k < ORIG; k++){
            float2 w = *(const float2*)&sW[k*AF + lane*2];
            #pragma unroll
            for (int r = 0; r < 4; r++){
                float xv = sIn[warp][r*ORIG + k];
                acc[r][0] = fmaf(xv, w.x, acc[r][0]);
                acc[r][1] = fmaf(xv, w.y, acc[r][1]);
            }
        }
        #pragma unroll
        for (int r = 0; r < 4; r++)
            *(float2*)&g_x[(base+r)*AF + lane*2] = make_float2(acc[r][0], acc[r][1]);
        __syncwarp();
    }
}

// ---------------- P/Q GEMM core (HFMA2, dual parity chains) --------------
__device__ __forceinline__ void pq_gemm_body(const uint4* sWq, const __half2* sXw,
                                             int base){
    __half2 z = __float2half2_rn(0.f);
    __half2 aA[2][4] = {{z,z,z,z},{z,z,z,z}};
    __half2 aB[2][4] = {{z,z,z,z},{z,z,z,z}};
    int lane = threadIdx.x & 31;
    #pragma unroll 4
    for (int kp = 0; kp < 32; kp++){
        uint4 wAu = sWq[(2*kp)*32 + lane];
        uint4 wBu = sWq[(2*kp+1)*32 + lane];
        __half2 wA[4] = {*(__half2*)&wAu.x, *(__half2*)&wAu.y,
                         *(__half2*)&wAu.z, *(__half2*)&wAu.w};
        __half2 wB[4] = {*(__half2*)&wBu.x, *(__half2*)&wBu.y,
                         *(__half2*)&wBu.z, *(__half2*)&wBu.w};
        #pragma unroll
        for (int a = 0; a < 2; a++){
            __half2 ep = sXw[a*33 + kp];
            __half2 eA = __low2half2(ep), eB = __high2half2(ep);
            #pragma unroll
            for (int c = 0; c < 4; c++){
                aA[a][c] = __hfma2(eA, wA[c], aA[a][c]);
                aB[a][c] = __hfma2(eB, wB[c], aB[a][c]);
            }
        }
    }
    #pragma unroll
    for (int a = 0; a < 2; a++){
        float2 f[4];
        #pragma unroll
        for (int c = 0; c < 4; c++)
            f[c] = __half22float2(__hadd2(aA[a][c], aB[a][c]));
        float* dst = (lane < 16) ? &g_P[(size_t)(base+a)*G1 + lane*8]
                                 : &g_Q[(size_t)(base+a)*G1 + (lane-16)*8];
        *(float4*)dst       = make_float4(f[0].x, f[0].y, f[1].x, f[1].y);
        *(float4*)(dst + 4) = make_float4(f[2].x, f[2].y, f[3].x, f[3].y);
    }
}

__device__ __forceinline__ void load_pq_weights(uint4* sWq, const float* Wf){
    __half2* sWh = (__half2*)sWq;
    int tid = threadIdx.x;
    for (int i = tid; i < 64*128; i += 256){
        int k = i >> 7, cp = i & 127;
        int c0 = cp*2, c1 = cp*2 + 1;
        float w0 = (c0 < G1) ? Wf[k*G1 + c0] : Wf[(AF + k)*G1 + (c0 - G1)];
        float w1 = (c1 < G1) ? Wf[k*G1 + c1] : Wf[(AF + k)*G1 + (c1 - G1)];
        sWh[k*128 + cp] = __floats2half2_rn(w0, w1);
    }
}

// ---------------- standalone P/Q GEMM (layer 0) ---------------------------
__global__ void __launch_bounds__(256) kPQ2(const float* __restrict__ Wf){
    __shared__ uint4 sWq[64*32];
    __shared__ __half2 sX[8][2*33];
    int tid = threadIdx.x, wid = tid >> 5, lane = tid & 31;
    load_pq_weights(sWq, Wf);
    __syncthreads();
    int gw = blockIdx.x*8 + wid, nw = gridDim.x*8;
    for (int grp = gw; grp < N_ATOMSC/2; grp += nw){
        int base = grp*2;
        for (int i = lane; i < 64; i += 32){
            int a = i >> 5, kp = i & 31;
            sX[wid][a*33 + kp] = __floats2half2_rn(g_x[(base+a)*AF + kp*2],
                                                   g_x[(base+a)*AF + kp*2 + 1]);
        }
        __syncwarp();
        pq_gemm_body(sWq, sX[wid], base);
        __syncwarp();
    }
}

// ---------------- fused residual update + next-layer P/Q GEMM ------------
__global__ void __launch_bounds__(256) kUpdatePQ(const float* __restrict__ WfNext){
    __shared__ uint4 sWq[64*32];
    __shared__ __half2 sX[8][2*33];
    int tid = threadIdx.x, wid = tid >> 5, lane = tid & 31;
    load_pq_weights(sWq, WfNext);
    __syncthreads();
    int gw = blockIdx.x*8 + wid, nw = gridDim.x*8;
    for (int grp = gw; grp < N_ATOMSC/2; grp += nw){
        int base = grp*2;
        for (int i = lane; i < 64; i += 32){
            int a = i >> 5, kp = i & 31;
            size_t off = (size_t)(base+a)*AF + kp*2;
            float2 xv = *(const float2*)&g_x[off];
            float2 nv = *(const float2*)&g_ns[off];
            float2 a2 = *(const float2*)&g_a2[kp*2];
            float2 b2 = *(const float2*)&g_b2[kp*2];
            float x0 = softplus_fast(xv.x + fmaf(nv.x, a2.x, b2.x));
            float x1 = softplus_fast(xv.y + fmaf(nv.y, a2.y, b2.y));
            *(float2*)&g_x[off] = make_float2(x0, x1);
            sX[wid][a*33 + kp] = __floats2half2_rn(x0, x1);
        }
        __syncwarp();
        pq_gemm_body(sWq, sX[wid], base);
        __syncwarp();
    }
}

// ---------------- edge kernel: 12 rows/warp, MERGED chains, 3 blocks/SM --
__global__ void __launch_bounds__(256, 3) kEdgeH(const int*   __restrict__ NI,
                                                 const float* __restrict__ Wf,
                                                 const float* __restrict__ bf){
    __shared__ uint2 sWq[42*32];                  // 10752 B
    __shared__ float sb[G1], sS[G1], sQ[G1];
    __shared__ __align__(16) __half2 sE[8][256];  // 8192 B
    int tid = threadIdx.x, wid = tid >> 5, lane = tid & 31;
    const float* WfE = Wf + 128*G1;
    __half2* sWh = (__half2*)sWq;
    for (int i = tid; i < NBRF*64; i += 256){
        int k = i >> 6, cp = i & 63;
        sWh[k*64 + cp] = __floats2half2_rn(WfE[k*G1 + cp*2], WfE[k*G1 + cp*2 + 1]);
    }
    for (int i = NBRF*64 + tid; i < 42*64; i += 256) sWh[i] = __float2half2_rn(0.f);
    if (tid < G1){ sb[tid] = bf[tid]; sS[tid] = 0.f; sQ[tid] = 0.f; }
    __syncthreads();

    float4 bb = *(const float4*)&sb[lane*4];
    float cs[4] = {0,0,0,0}, cq[4] = {0,0,0,0};

    const uint4* Eh4 = (const uint4*)g_Eh;
    int gw = blockIdx.x*8 + wid, nw = gridDim.x*8;
    uint4 er0, er1;
    if (gw < N_ATOMSC){
        er0 = Eh4[(size_t)gw*64 + lane];
        er1 = Eh4[(size_t)gw*64 + 32 + lane];
    }

    for (int n = gw; n < N_ATOMSC; n += nw){
        ((uint4*)sE[wid])[lane]      = er0;
        ((uint4*)sE[wid])[lane + 32] = er1;
        __syncwarp();
        int nn = n + nw;
        if (nn < N_ATOMSC){
            er0 = Eh4[(size_t)nn*64 + lane];
            er1 = Eh4[(size_t)nn*64 + 32 + lane];
        }

        size_t rb = (size_t)n * 12;
        int4 j0 = *(const int4*)&NI[rb];
        int4 j1 = *(const int4*)&NI[rb + 4];
        int4 j2 = *(const int4*)&NI[rb + 8];
        int jj[12] = {j0.x,j0.y,j0.z,j0.w, j1.x,j1.y,j1.z,j1.w, j2.x,j2.y,j2.z,j2.w};
        float4 p = *(const float4*)&g_P[(size_t)n*G1 + lane*4];
        float4 pqb = make_float4(p.x + bb.x, p.y + bb.y, p.z + bb.z, p.w + bb.w);

        __half2 z = __float2half2_rn(0.f);
        __half2 acc[12][2];
        #pragma unroll
        for (int r = 0; r < 12; r++){ acc[r][0] = z; acc[r][1] = z; }
        #pragma unroll 3
        for (int kp = 0; kp < 21; kp++){
            uint2 wAu = sWq[(2*kp)*32 + lane];
            uint2 wBu = sWq[(2*kp+1)*32 + lane];
            __half2 wA0 = *(__half2*)&wAu.x, wA1 = *(__half2*)&wAu.y;
            __half2 wB0 = *(__half2*)&wBu.x, wB1 = *(__half2*)&wBu.y;
            #pragma unroll
            for (int r = 0; r < 12; r++){
                __half2 ep = sE[wid][r*21 + kp];
                __half2 eA = __low2half2(ep), eB = __high2half2(ep);
                acc[r][0] = __hfma2(eA, wA0, acc[r][0]);
                acc[r][1] = __hfma2(eA, wA1, acc[r][1]);
                acc[r][0] = __hfma2(eB, wB0, acc[r][0]);
                acc[r][1] = __hfma2(eB, wB1, acc[r][1]);
            }
        }
        #pragma unroll
        for (int r = 0; r < 12; r++){
            float4 q = *(const float4*)&g_Q[(size_t)jj[r]*G1 + lane*4];
            float2 f0 = __half22float2(acc[r][0]);
            float2 f1 = __half22float2(acc[r][1]);
            float v0 = f0.x + pqb.x + q.x;
            float v1 = f0.y + pqb.y + q.y;
            float v2 = f1.x + pqb.z + q.z;
            float v3 = f1.y + pqb.w + q.w;
            cs[0] += v0; cq[0] = fmaf(v0, v0, cq[0]);
            cs[1] += v1; cq[1] = fmaf(v1, v1, cq[1]);
            cs[2] += v2; cq[2] = fmaf(v2, v2, cq[2]);
            cs[3] += v3; cq[3] = fmaf(v3, v3, cq[3]);
            __half2 h0 = __floats2half2_rn(v0, v1);
            __half2 h1 = __floats2half2_rn(v2, v3);
            *(uint2*)&g_gated[(rb + r)*(G1/2) + lane*2] =
                make_uint2(*(unsigned*)&h0, *(unsigned*)&h1);
        }
        __syncwarp();
    }
    atomicAdd(&sS[lane*4+0], cs[0]); atomicAdd(&sQ[lane*4+0], cq[0]);
    atomicAdd(&sS[lane*4+1], cs[1]); atomicAdd(&sQ[lane*4+1], cq[1]);
    atomicAdd(&sS[lane*4+2], cs[2]); atomicAdd(&sQ[lane*4+2], cq[2]);
    atomicAdd(&sS[lane*4+3], cs[3]); atomicAdd(&sQ[lane*4+3], cq[3]);
    __syncthreads();
    if (tid < G1){
        atomicAdd(&g_s1[tid],  sS[tid]);
        atomicAdd(&g_ss1[tid], sQ[tid]);
    }
}

// ---------------- reduce: inline BN1 fold + sigmoid*softplus --------------
__global__ void __launch_bounds__(256) kReduce(const float* __restrict__ gam1,
                                               const float* __restrict__ bet1){
    __shared__ float rs[AF], rq[AF];
    int tid = threadIdx.x;
    int wid = tid >> 5, lane = tid & 31;
    if (tid < AF){ rs[tid] = 0.f; rq[tid] = 0.f; }
    int f2 = lane*2;
    float A1x, A1y, B1x, B1y, A2x, A2y, B2x, B2y;
    {
        const float inv = 1.f / (float)NM;
        #pragma unroll
        for (int t = 0; t < 4; t++){
            int f = (t >> 1) ? (64 + f2 + (t & 1)) : (f2 + (t & 1));
            float m = g_s1[f]*inv;
            float v = g_ss1[f]*inv - m*m;
            float a = gam1[f] * rsqrtf(v + EPSL);
            float bb = bet1[f] - m*a;
            if (t == 0){ A1x = a; B1x = bb; }
            else if (t == 1){ A1y = a; B1y = bb; }
            else if (t == 2){ A2x = a; B2x = bb; }
            else { A2y = a; B2y = bb; }
        }
    }
    __syncthreads();
    float s0=0,s1=0,q0=0,q1=0;
    int gw = blockIdx.x*8 + wid, nw = gridDim.x*8;
    for (int n = gw; n < N_ATOMSC; n += nw){
        const __half2* bh = g_gated + (size_t)n*(M_NBR*(G1/2)) + lane;
        __half2 hf[M_NBR], hc[M_NBR];
        #pragma unroll
        for (int m = 0; m < M_NBR; m++){
            hf[m] = bh[m*64];
            hc[m] = bh[m*64 + 32];
        }
        float a0 = 0.f, a1 = 0.f;
        #pragma unroll
        for (int m = 0; m < M_NBR; m++){
            float2 zf = __half22float2(hf[m]);
            float2 zc = __half22float2(hc[m]);
            float xf0 = fmaf(zf.x, A1x, B1x);
            float xf1 = fmaf(zf.y, A1y, B1y);
            float xc0 = fmaf(zc.x, A2x, B2x);
            float xc1 = fmaf(zc.y, A2y, B2y);
            float sg0 = sigmoid_tanh(xf0);
            float sg1 = sigmoid_tanh(xf1);
            a0 = fmaf(sg0, softplus_fast(xc0), a0);
            a1 = fmaf(sg1, softplus_fast(xc1), a1);
        }
        *(float2*)&g_ns[(size_t)n*AF + f2] = make_float2(a0, a1);
        s0 += a0; q0 = fmaf(a0, a0, q0);
        s1 += a1; q1 = fmaf(a1, a1, q1);
    }
    atomicAdd(&rs[f2],   s0); atomicAdd(&rq[f2],   q0);
    atomicAdd(&rs[f2+1], s1); atomicAdd(&rq[f2+1], q1);
    __syncthreads();
    if (tid < AF){
        atomicAdd(&g_s2[tid],  rs[tid]);
        atomicAdd(&g_ss2[tid], rq[tid]);
    }
}

// ---------------- BN2 finalize + BN1 stat reset ---------------------------
__global__ void kBN2(const float* __restrict__ gam, const float* __restrict__ bet){
    int f = threadIdx.x;
    float inv = 1.f / (float)N_ATOMSC;
    float m = g_s2[f]*inv;
    float v = g_ss2[f]*inv - m*m;
    float a = gam[f] * rsqrtf(v + EPSL);
    g_a2[f] = a;
    g_b2[f] = bet[f] - m*a;
    g_s2[f] = 0.f; g_ss2[f] = 0.f;
    g_s1[f] = 0.f;      g_ss1[f] = 0.f;
    g_s1[f+64] = 0.f;   g_ss1[f+64] = 0.f;
}

// ---------------- plain residual update (last layer) ---------------------
__global__ void __launch_bounds__(256) kUpdate(){
    int i4 = blockIdx.x*256 + threadIdx.x;
    int f = (i4 & 15) * 4;
    float4 xv = *(const float4*)&g_x[i4*4];
    float4 nv = *(const float4*)&g_ns[i4*4];
    float4 a2 = *(const float4*)&g_a2[f];
    float4 b2 = *(const float4*)&g_b2[f];
    float4 o;
    o.x = softplus_fast(xv.x + fmaf(nv.x, a2.x, b2.x));
    o.y = softplus_fast(xv.y + fmaf(nv.y, a2.y, b2.y));
    o.z = softplus_fast(xv.z + fmaf(nv.z, a2.z, b2.z));
    o.w = softplus_fast(xv.w + fmaf(nv.w, a2.w, b2.w));
    *(float4*)&g_x[i4*4] = o;
}

// ---------------- pool + FC + ReLU ---------------------------------------
__global__ void __launch_bounds__(128) kPool(const int* __restrict__ cidx,
                                             const float* __restrict__ Wp,
                                             const float* __restrict__ bp,
                                             float* __restrict__ out){
    __shared__ float sm[AF];
    int c = blockIdx.x, tid = threadIdx.x;
    if (tid < AF){
        float s = 0.f;
        #pragma unroll 5
        for (int a = 0; a < APC; a++){
            int idx = cidx[c*APC + a];
            s += g_x[idx*AF + tid];
        }
        sm[tid] = s * (1.f/(float)APC);
    }
    __syncthreads();
    float acc = bp[tid];
    #pragma unroll 8
    for (int k = 0; k < AF; k++)
        acc = fmaf(sm[k], Wp[k*OUTD + tid], acc);
    out[c*OUTD + tid] = fmaxf(acc, 0.f);
}

// ---------------- launcher ------------------------------------------------
extern "C" void kernel_launch(void* const* d_in, const int* in_sizes, int n_in,
                              void* d_out, int out_size){
    const float* atom_fea = (const float*)d_in[0];
    const float* nbr_fea  = (const float*)d_in[1];
    const int*   nbr_idx  = (const int*)  d_in[2];
    const int*   cidx     = (const int*)  d_in[3];
    const float* W_embed  = (const float*)d_in[4];
    const float* b_embed  = (const float*)d_in[5];
    const float* W_full   = (const float*)d_in[6];
    const float* b_full   = (const float*)d_in[7];
    const float* g1       = (const float*)d_in[8];
    const float* be1      = (const float*)d_in[9];
    const float* g2       = (const float*)d_in[10];
    const float* be2      = (const float*)d_in[11];
    const float* Wp       = (const float*)d_in[12];
    const float* bp       = (const float*)d_in[13];
    float* out = (float*)d_out;

    kEmbedPrep<<<EMB_BLKS + N_ATOMSC, 256>>>(atom_fea, W_embed, b_embed, nbr_fea); // 0
    kPQ2<<<592, 256>>>(W_full);                                                    // 1
    for (int l = 0; l < 3; l++){
        const float* Wf = W_full + (size_t)l * 169 * G1;
        kEdgeH <<<444, 256>>>(nbr_idx, Wf, b_full + l*G1);   // l==0 -> launch 2
        kReduce<<<1184, 256>>>(g1 + l*G1, be1 + l*G1);       // l==0 -> launch 3
        kBN2   <<<1, 64>>>(g2 + l*AF, be2 + l*AF);
        if (l < 2){
            const float* WfN = W_full + (size_t)(l+1) * 169 * G1;
            kUpdatePQ<<<592, 256>>>(WfN);
        } else {
            kUpdate<<<(N_ATOMSC*AF/4)/256, 256>>>();
        }
    }
    kPool<<<NCRY, 128>>>(cidx, Wp, bp, out);
}

// round 16
// speedup vs baseline: 1.1981x; 1.0116x over previous
#include <cuda_runtime.h>
#include <cuda_fp16.h>
#include <math.h>
#include <stdint.h>

#define N_ATOMSC 100000
#define M_NBR    12
#define ORIG     92
#define NBRF     41
#define AF       64
#define G1       128
#define NM       (N_ATOMSC*M_NBR)
#define OUTD     128
#define NCRY     2000
#define APC      50
#define EPSL     1e-5f

#define EMB_BLKS 512

// ---------------- device scratch ----------------------------------------
__device__ float   g_x[N_ATOMSC*AF];
__device__ float   g_P[N_ATOMSC*G1];
__device__ float   g_Q[N_ATOMSC*G1];
__device__ __half2 g_gated[(size_t)NM*(G1/2)];       // fp16 gated (307 MB)
__device__ __align__(16) __half2 g_Eh[(size_t)N_ATOMSC*256];  // packed E pairs (102 MB)
__device__ float   g_ns[N_ATOMSC*AF];
__device__ float   g_s1[G1], g_ss1[G1];
__device__ float   g_s2[AF], g_ss2[AF], g_a2[AF], g_b2[AF];

__device__ __forceinline__ float softplus_fast(float x){
    return fmaxf(x, 0.f) + __logf(1.f + __expf(-fabsf(x)));
}
__device__ __forceinline__ float sigmoid_tanh(float x){
    float t;
    asm("tanh.approx.f32 %0, %1;" : "=f"(t) : "f"(0.5f*x));
    return fmaf(0.5f, t, 0.5f);
}

// ---------------- fused embed + E preconversion --------------------------
__global__ void __launch_bounds__(256) kEmbedPrep(const float* __restrict__ A,
                                                  const float* __restrict__ W,
                                                  const float* __restrict__ b,
                                                  const float* __restrict__ E){
    __shared__ float sW[ORIG*AF];
    __shared__ float sb_[AF];
    __shared__ float sIn[8][4*ORIG];
    int tid = threadIdx.x;
    if (blockIdx.x >= EMB_BLKS){
        int idx = (blockIdx.x - EMB_BLKS)*256 + tid;
        int o = idx & 255;
        if (o >= 252){ g_Eh[idx] = __float2half2_rn(0.f); return; }
        int atom = idx >> 8;
        int r = o / 21, kp = o - r*21;
        size_t row = (size_t)atom*12 + r;
        float e0 = E[row*NBRF + kp*2];
        float e1 = (kp < 20) ? E[row*NBRF + kp*2 + 1] : 0.f;
        g_Eh[idx] = __floats2half2_rn(e0, e1);
        return;
    }
    for (int i = tid; i < ORIG*AF; i += 256) sW[i] = W[i];
    if (tid < AF) sb_[tid] = b[tid];
    __syncthreads();
    int warp = tid >> 5, lane = tid & 31;
    int gw = blockIdx.x*8 + warp, nw = EMB_BLKS*8;
    float b0 = sb_[lane*2], b1 = sb_[lane*2+1];
    for (int grp = gw; grp < N_ATOMSC/4; grp += nw){
        int base = grp*4;
        for (int i = lane; i < 4*ORIG; i += 32)
            sIn[warp][i] = A[base*ORIG + i];
        __syncwarp();
        float acc[4][2];
        #pragma unroll
        for (int r = 0; r < 4; r++){ acc[r][0] = b0; acc[r][1] = b1; }
        #pragma unroll 4
        for (int k = 0; k < ORIG; k++){
            float2 w = *(const float2*)&sW[k*AF + lane*2];
            #pragma unroll
            for (int r = 0; r < 4; r++){
                float xv = sIn[warp][r*ORIG + k];
                acc[r][0] = fmaf(xv, w.x, acc[r][0]);
                acc[r][1] = fmaf(xv, w.y, acc[r][1]);
            }
        }
        #pragma unroll
        for (int r = 0; r < 4; r++)
            *(float2*)&g_x[(base+r)*AF + lane*2] = make_float2(acc[r][0], acc[r][1]);
        __syncwarp();
    }
}

// ---------------- P/Q GEMM core: 4 atoms/warp, merged chains -------------
// lane owns 8 cols (4 half2) of the 256-col [P|Q] concat.
__device__ __forceinline__ void pq_gemm_body4(const uint4* sWq, const __half2* sXw,
                                              int base){
    __half2 z = __float2half2_rn(0.f);
    __half2 acc[4][4] = {{z,z,z,z},{z,z,z,z},{z,z,z,z},{z,z,z,z}};
    int lane = threadIdx.x & 31;
    #pragma unroll 4
    for (int kp = 0; kp < 32; kp++){
        uint4 wAu = sWq[(2*kp)*32 + lane];
        uint4 wBu = sWq[(2*kp+1)*32 + lane];
        __half2 wA[4] = {*(__half2*)&wAu.x, *(__half2*)&wAu.y,
                         *(__half2*)&wAu.z, *(__half2*)&wAu.w};
        __half2 wB[4] = {*(__half2*)&wBu.x, *(__half2*)&wBu.y,
                         *(__half2*)&wBu.z, *(__half2*)&wBu.w};
        #pragma unroll
        for (int a = 0; a < 4; a++){
            __half2 ep = sXw[a*33 + kp];
            __half2 eA = __low2half2(ep), eB = __high2half2(ep);
            #pragma unroll
            for (int c = 0; c < 4; c++){
                acc[a][c] = __hfma2(eA, wA[c], acc[a][c]);
                acc[a][c] = __hfma2(eB, wB[c], acc[a][c]);
            }
        }
    }
    #pragma unroll
    for (int a = 0; a < 4; a++){
        float2 f[4];
        #pragma unroll
        for (int c = 0; c < 4; c++)
            f[c] = __half22float2(acc[a][c]);
        float* dst = (lane < 16) ? &g_P[(size_t)(base+a)*G1 + lane*8]
                                 : &g_Q[(size_t)(base+a)*G1 + (lane-16)*8];
        *(float4*)dst       = make_float4(f[0].x, f[0].y, f[1].x, f[1].y);
        *(float4*)(dst + 4) = make_float4(f[2].x, f[2].y, f[3].x, f[3].y);
    }
}

__device__ __forceinline__ void load_pq_weights(uint4* sWq, const float* Wf){
    __half2* sWh = (__half2*)sWq;
    int tid = threadIdx.x;
    for (int i = tid; i < 64*128; i += 256){
        int k = i >> 7, cp = i & 127;
        int c0 = cp*2, c1 = cp*2 + 1;
        float w0 = (c0 < G1) ? Wf[k*G1 + c0] : Wf[(AF + k)*G1 + (c0 - G1)];
        float w1 = (c1 < G1) ? Wf[k*G1 + c1] : Wf[(AF + k)*G1 + (c1 - G1)];
        sWh[k*128 + cp] = __floats2half2_rn(w0, w1);
    }
}

// ---------------- standalone P/Q GEMM (layer 0) ---------------------------
__global__ void __launch_bounds__(256) kPQ2(const float* __restrict__ Wf){
    __shared__ uint4 sWq[64*32];          // 32768 B
    __shared__ __half2 sX[8][4*33];       // 4 atoms per warp
    int tid = threadIdx.x, wid = tid >> 5, lane = tid & 31;
    load_pq_weights(sWq, Wf);
    __syncthreads();
    int gw = blockIdx.x*8 + wid, nw = gridDim.x*8;
    for (int grp = gw; grp < N_ATOMSC/4; grp += nw){
        int base = grp*4;
        #pragma unroll
        for (int i = lane; i < 128; i += 32){
            int a = i >> 5, kp = i & 31;
            sX[wid][a*33 + kp] = __floats2half2_rn(g_x[(base+a)*AF + kp*2],
                                                   g_x[(base+a)*AF + kp*2 + 1]);
        }
        __syncwarp();
        pq_gemm_body4(sWq, sX[wid], base);
        __syncwarp();
    }
}

// ---------------- fused residual update + next-layer P/Q GEMM ------------
__global__ void __launch_bounds__(256) kUpdatePQ(const float* __restrict__ WfNext){
    __shared__ uint4 sWq[64*32];
    __shared__ __half2 sX[8][4*33];
    int tid = threadIdx.x, wid = tid >> 5, lane = tid & 31;
    load_pq_weights(sWq, WfNext);
    __syncthreads();
    int gw = blockIdx.x*8 + wid, nw = gridDim.x*8;
    for (int grp = gw; grp < N_ATOMSC/4; grp += nw){
        int base = grp*4;
        #pragma unroll
        for (int i = lane; i < 128; i += 32){
            int a = i >> 5, kp = i & 31;
            size_t off = (size_t)(base+a)*AF + kp*2;
            float2 xv = *(const float2*)&g_x[off];
            float2 nv = *(const float2*)&g_ns[off];
            float2 a2 = *(const float2*)&g_a2[kp*2];
            float2 b2 = *(const float2*)&g_b2[kp*2];
            float x0 = softplus_fast(xv.x + fmaf(nv.x, a2.x, b2.x));
            float x1 = softplus_fast(xv.y + fmaf(nv.y, a2.y, b2.y));
            *(float2*)&g_x[off] = make_float2(x0, x1);
            sX[wid][a*33 + kp] = __floats2half2_rn(x0, x1);
        }
        __syncwarp();
        pq_gemm_body4(sWq, sX[wid], base);
        __syncwarp();
    }
}

// ---------------- edge kernel: 12 rows/warp, MERGED chains, 3 blocks/SM --
__global__ void __launch_bounds__(256, 3) kEdgeH(const int*   __restrict__ NI,
                                                 const float* __restrict__ Wf,
                                                 const float* __restrict__ bf){
    __shared__ uint2 sWq[42*32];                  // 10752 B
    __shared__ float sb[G1], sS[G1], sQ[G1];
    __shared__ __align__(16) __half2 sE[8][256];  // 8192 B
    int tid = threadIdx.x, wid = tid >> 5, lane = tid & 31;
    const float* WfE = Wf + 128*G1;
    __half2* sWh = (__half2*)sWq;
    for (int i = tid; i < NBRF*64; i += 256){
        int k = i >> 6, cp = i & 63;
        sWh[k*64 + cp] = __floats2half2_rn(WfE[k*G1 + cp*2], WfE[k*G1 + cp*2 + 1]);
    }
    for (int i = NBRF*64 + tid; i < 42*64; i += 256) sWh[i] = __float2half2_rn(0.f);
    if (tid < G1){ sb[tid] = bf[tid]; sS[tid] = 0.f; sQ[tid] = 0.f; }
    __syncthreads();

    float4 bb = *(const float4*)&sb[lane*4];
    float cs[4] = {0,0,0,0}, cq[4] = {0,0,0,0};

    const uint4* Eh4 = (const uint4*)g_Eh;
    int gw = blockIdx.x*8 + wid, nw = gridDim.x*8;
    uint4 er0, er1;
    if (gw < N_ATOMSC){
        er0 = Eh4[(size_t)gw*64 + lane];
        er1 = Eh4[(size_t)gw*64 + 32 + lane];
    }

    for (int n = gw; n < N_ATOMSC; n += nw){
        ((uint4*)sE[wid])[lane]      = er0;
        ((uint4*)sE[wid])[lane + 32] = er1;
        __syncwarp();
        int nn = n + nw;
        if (nn < N_ATOMSC){
            er0 = Eh4[(size_t)nn*64 + lane];
            er1 = Eh4[(size_t)nn*64 + 32 + lane];
        }

        size_t rb = (size_t)n * 12;
        int4 j0 = *(const int4*)&NI[rb];
        int4 j1 = *(const int4*)&NI[rb + 4];
        int4 j2 = *(const int4*)&NI[rb + 8];
        int jj[12] = {j0.x,j0.y,j0.z,j0.w, j1.x,j1.y,j1.z,j1.w, j2.x,j2.y,j2.z,j2.w};
        float4 p = *(const float4*)&g_P[(size_t)n*G1 + lane*4];
        float4 pqb = make_float4(p.x + bb.x, p.y + bb.y, p.z + bb.z, p.w + bb.w);

        __half2 z = __float2half2_rn(0.f);
        __half2 acc[12][2];
        #pragma unroll
        for (int r = 0; r < 12; r++){ acc[r][0] = z; acc[r][1] = z; }
        #pragma unroll 3
        for (int kp = 0; kp < 21; kp++){
            uint2 wAu = sWq[(2*kp)*32 + lane];
            uint2 wBu = sWq[(2*kp+1)*32 + lane];
            __half2 wA0 = *(__half2*)&wAu.x, wA1 = *(__half2*)&wAu.y;
            __half2 wB0 = *(__half2*)&wBu.x, wB1 = *(__half2*)&wBu.y;
            #pragma unroll
            for (int r = 0; r < 12; r++){
                __half2 ep = sE[wid][r*21 + kp];
                __half2 eA = __low2half2(ep), eB = __high2half2(ep);
                acc[r][0] = __hfma2(eA, wA0, acc[r][0]);
                acc[r][1] = __hfma2(eA, wA1, acc[r][1]);
                acc[r][0] = __hfma2(eB, wB0, acc[r][0]);
                acc[r][1] = __hfma2(eB, wB1, acc[r][1]);
            }
        }
        #pragma unroll
        for (int r = 0; r < 12; r++){
            float4 q = *(const float4*)&g_Q[(size_t)jj[r]*G1 + lane*4];
            float2 f0 = __half22float2(acc[r][0]);
            float2 f1 = __half22float2(acc[r][1]);
            float v0 = f0.x + pqb.x + q.x;
            float v1 = f0.y + pqb.y + q.y;
            float v2 = f1.x + pqb.z + q.z;
            float v3 = f1.y + pqb.w + q.w;
            cs[0] += v0; cq[0] = fmaf(v0, v0, cq[0]);
            cs[1] += v1; cq[1] = fmaf(v1, v1, cq[1]);
            cs[2] += v2; cq[2] = fmaf(v2, v2, cq[2]);
            cs[3] += v3; cq[3] = fmaf(v3, v3, cq[3]);
            __half2 h0 = __floats2half2_rn(v0, v1);
            __half2 h1 = __floats2half2_rn(v2, v3);
            *(uint2*)&g_gated[(rb + r)*(G1/2) + lane*2] =
                make_uint2(*(unsigned*)&h0, *(unsigned*)&h1);
        }
        __syncwarp();
    }
    atomicAdd(&sS[lane*4+0], cs[0]); atomicAdd(&sQ[lane*4+0], cq[0]);
    atomicAdd(&sS[lane*4+1], cs[1]); atomicAdd(&sQ[lane*4+1], cq[1]);
    atomicAdd(&sS[lane*4+2], cs[2]); atomicAdd(&sQ[lane*4+2], cq[2]);
    atomicAdd(&sS[lane*4+3], cs[3]); atomicAdd(&sQ[lane*4+3], cq[3]);
    __syncthreads();
    if (tid < G1){
        atomicAdd(&g_s1[tid],  sS[tid]);
        atomicAdd(&g_ss1[tid], sQ[tid]);
    }
}

// ---------------- reduce: inline BN1 fold + sigmoid*softplus --------------
__global__ void __launch_bounds__(256) kReduce(const float* __restrict__ gam1,
                                               const float* __restrict__ bet1){
    __shared__ float rs[AF], rq[AF];
    int tid = threadIdx.x;
    int wid = tid >> 5, lane = tid & 31;
    if (tid < AF){ rs[tid] = 0.f; rq[tid] = 0.f; }
    int f2 = lane*2;
    float A1x, A1y, B1x, B1y, A2x, A2y, B2x, B2y;
    {
        const float inv = 1.f / (float)NM;
        #pragma unroll
        for (int t = 0; t < 4; t++){
            int f = (t >> 1) ? (64 + f2 + (t & 1)) : (f2 + (t & 1));
            float m = g_s1[f]*inv;
            float v = g_ss1[f]*inv - m*m;
            float a = gam1[f] * rsqrtf(v + EPSL);
            float bb = bet1[f] - m*a;
            if (t == 0){ A1x = a; B1x = bb; }
            else if (t == 1){ A1y = a; B1y = bb; }
            else if (t == 2){ A2x = a; B2x = bb; }
            else { A2y = a; B2y = bb; }
        }
    }
    __syncthreads();
    float s0=0,s1=0,q0=0,q1=0;
    int gw = blockIdx.x*8 + wid, nw = gridDim.x*8;
    for (int n = gw; n < N_ATOMSC; n += nw){
        const __half2* bh = g_gated + (size_t)n*(M_NBR*(G1/2)) + lane;
        __half2 hf[M_NBR], hc[M_NBR];
        #pragma unroll
        for (int m = 0; m < M_NBR; m++){
            hf[m] = bh[m*64];
            hc[m] = bh[m*64 + 32];
        }
        float a0 = 0.f, a1 = 0.f;
        #pragma unroll
        for (int m = 0; m < M_NBR; m++){
            float2 zf = __half22float2(hf[m]);
            float2 zc = __half22float2(hc[m]);
            float xf0 = fmaf(zf.x, A1x, B1x);
            float xf1 = fmaf(zf.y, A1y, B1y);
            float xc0 = fmaf(zc.x, A2x, B2x);
            float xc1 = fmaf(zc.y, A2y, B2y);
            float sg0 = sigmoid_tanh(xf0);
            float sg1 = sigmoid_tanh(xf1);
            a0 = fmaf(sg0, softplus_fast(xc0), a0);
            a1 = fmaf(sg1, softplus_fast(xc1), a1);
        }
        *(float2*)&g_ns[(size_t)n*AF + f2] = make_float2(a0, a1);
        s0 += a0; q0 = fmaf(a0, a0, q0);
        s1 += a1; q1 = fmaf(a1, a1, q1);
    }
    atomicAdd(&rs[f2],   s0); atomicAdd(&rq[f2],   q0);
    atomicAdd(&rs[f2+1], s1); atomicAdd(&rq[f2+1], q1);
    __syncthreads();
    if (tid < AF){
        atomicAdd(&g_s2[tid],  rs[tid]);
        atomicAdd(&g_ss2[tid], rq[tid]);
    }
}

// ---------------- BN2 finalize + BN1 stat reset ---------------------------
__global__ void kBN2(const float* __restrict__ gam, const float* __restrict__ bet){
    int f = threadIdx.x;
    float inv = 1.f / (float)N_ATOMSC;
    float m = g_s2[f]*inv;
    float v = g_ss2[f]*inv - m*m;
    float a = gam[f] * rsqrtf(v + EPSL);
    g_a2[f] = a;
    g_b2[f] = bet[f] - m*a;
    g_s2[f] = 0.f; g_ss2[f] = 0.f;
    g_s1[f] = 0.f;      g_ss1[f] = 0.f;
    g_s1[f+64] = 0.f;   g_ss1[f+64] = 0.f;
}

// ---------------- plain residual update (last layer) ---------------------
__global__ void __launch_bounds__(256) kUpdate(){
    int i4 = blockIdx.x*256 + threadIdx.x;
    int f = (i4 & 15) * 4;
    float4 xv = *(const float4*)&g_x[i4*4];
    float4 nv = *(const float4*)&g_ns[i4*4];
    float4 a2 = *(const float4*)&g_a2[f];
    float4 b2 = *(const float4*)&g_b2[f];
    float4 o;
    o.x = softplus_fast(xv.x + fmaf(nv.x, a2.x, b2.x));
    o.y = softplus_fast(xv.y + fmaf(nv.y, a2.y, b2.y));
    o.z = softplus_fast(xv.z + fmaf(nv.z, a2.z, b2.z));
    o.w = softplus_fast(xv.w + fmaf(nv.w, a2.w, b2.w));
    *(float4*)&g_x[i4*4] = o;
}

// ---------------- pool + FC + ReLU ---------------------------------------
__global__ void __launch_bounds__(128) kPool(const int* __restrict__ cidx,
                                             const float* __restrict__ Wp,
                                             const float* __restrict__ bp,
                                             float* __restrict__ out){
    __shared__ float sm[AF];
    int c = blockIdx.x, tid = threadIdx.x;
    if (tid < AF){
        float s = 0.f;
        #pragma unroll 5
        for (int a = 0; a < APC; a++){
            int idx = cidx[c*APC + a];
            s += g_x[idx*AF + tid];
        }
        sm[tid] = s * (1.f/(float)APC);
    }
    __syncthreads();
    float acc = bp[tid];
    #pragma unroll 8
    for (int k = 0; k < AF; k++)
        acc = fmaf(sm[k], Wp[k*OUTD + tid], acc);
    out[c*OUTD + tid] = fmaxf(acc, 0.f);
}

// ---------------- launcher ------------------------------------------------
extern "C" void kernel_launch(void* const* d_in, const int* in_sizes, int n_in,
                              void* d_out, int out_size){
    const float* atom_fea = (const float*)d_in[0];
    const float* nbr_fea  = (const float*)d_in[1];
    const int*   nbr_idx  = (const int*)  d_in[2];
    const int*   cidx     = (const int*)  d_in[3];
    const float* W_embed  = (const float*)d_in[4];
    const float* b_embed  = (const float*)d_in[5];
    const float* W_full   = (const float*)d_in[6];
    const float* b_full   = (const float*)d_in[7];
    const float* g1       = (const float*)d_in[8];
    const float* be1      = (const float*)d_in[9];
    const float* g2       = (const float*)d_in[10];
    const float* be2      = (const float*)d_in[11];
    const float* Wp       = (const float*)d_in[12];
    const float* bp       = (const float*)d_in[13];
    float* out = (float*)d_out;

    kEmbedPrep<<<EMB_BLKS + N_ATOMSC, 256>>>(atom_fea, W_embed, b_embed, nbr_fea); // 0
    kPQ2<<<592, 256>>>(W_full);                                                    // 1
    for (int l = 0; l < 3; l++){
        const float* Wf = W_full + (size_t)l * 169 * G1;
        kEdgeH <<<444, 256>>>(nbr_idx, Wf, b_full + l*G1);   // l==0 -> launch 2
        kReduce<<<1184, 256>>>(g1 + l*G1, be1 + l*G1);       // l==0 -> launch 3
        kBN2   <<<1, 64>>>(g2 + l*AF, be2 + l*AF);
        if (l < 2){
            const float* WfN = W_full + (size_t)(l+1) * 169 * G1;
            kUpdatePQ<<<592, 256>>>(WfN);
        } else {
            kUpdate<<<(N_ATOMSC*AF/4)/256, 256>>>();
        }
    }
    kPool<<<NCRY, 128>>>(cidx, Wp, bp, out);
}

// round 17
// speedup vs baseline: 1.2387x; 1.0339x over previous
#include <cuda_runtime.h>
#include <cuda_fp16.h>
#include <math.h>
#include <stdint.h>

#define N_ATOMSC 100000
#define M_NBR    12
#define ORIG     92
#define NBRF     41
#define AF       64
#define G1       128
#define NM       (N_ATOMSC*M_NBR)
#define OUTD     128
#define NCRY     2000
#define APC      50
#define EPSL     1e-5f

#define EMB_BLKS 512

// ---------------- device scratch ----------------------------------------
__device__ float   g_x[N_ATOMSC*AF];
__device__ __align__(16) __half2 g_P[N_ATOMSC*64];   // fp16 P (25.6 MB)
__device__ __align__(16) __half2 g_Q[N_ATOMSC*64];   // fp16 Q (25.6 MB) -> L2-resident
__device__ __half2 g_gated[(size_t)NM*(G1/2)];       // fp16 gated (307 MB)
__device__ __align__(16) __half2 g_Eh[(size_t)N_ATOMSC*256];  // packed E pairs (102 MB)
__device__ float   g_ns[N_ATOMSC*AF];
__device__ float   g_s1[G1], g_ss1[G1];
__device__ float   g_s2[AF], g_ss2[AF], g_a2[AF], g_b2[AF];

__device__ __forceinline__ float softplus_fast(float x){
    return fmaxf(x, 0.f) + __logf(1.f + __expf(-fabsf(x)));
}
__device__ __forceinline__ float sigmoid_tanh(float x){
    float t;
    asm("tanh.approx.f32 %0, %1;" : "=f"(t) : "f"(0.5f*x));
    return fmaf(0.5f, t, 0.5f);
}

// ---------------- fused embed + E preconversion --------------------------
__global__ void __launch_bounds__(256) kEmbedPrep(const float* __restrict__ A,
                                                  const float* __restrict__ W,
                                                  const float* __restrict__ b,
                                                  const float* __restrict__ E){
    __shared__ float sW[ORIG*AF];
    __shared__ float sb_[AF];
    __shared__ float sIn[8][4*ORIG];
    int tid = threadIdx.x;
    if (blockIdx.x >= EMB_BLKS){
        int idx = (blockIdx.x - EMB_BLKS)*256 + tid;
        int o = idx & 255;
        if (o >= 252){ g_Eh[idx] = __float2half2_rn(0.f); return; }
        int atom = idx >> 8;
        int r = o / 21, kp = o - r*21;
        size_t row = (size_t)atom*12 + r;
        float e0 = E[row*NBRF + kp*2];
        float e1 = (kp < 20) ? E[row*NBRF + kp*2 + 1] : 0.f;
        g_Eh[idx] = __floats2half2_rn(e0, e1);
        return;
    }
    for (int i = tid; i < ORIG*AF; i += 256) sW[i] = W[i];
    if (tid < AF) sb_[tid] = b[tid];
    __syncthreads();
    int warp = tid >> 5, lane = tid & 31;
    int gw = blockIdx.x*8 + warp, nw = EMB_BLKS*8;
    float b0 = sb_[lane*2], b1 = sb_[lane*2+1];
    for (int grp = gw; grp < N_ATOMSC/4; grp += nw){
        int base = grp*4;
        for (int i = lane; i < 4*ORIG; i += 32)
            sIn[warp][i] = A[base*ORIG + i];
        __syncwarp();
        float acc[4][2];
        #pragma unroll
        for (int r = 0; r < 4; r++){ acc[r][0] = b0; acc[r][1] = b1; }
        #pragma unroll 4
        for (int k = 0; k < ORIG; k++){
            float2 w = *(const float2*)&sW[k*AF + lane*2];
            #pragma unroll
            for (int r = 0; r < 4; r++){
                float xv = sIn[warp][r*ORIG + k];
                acc[r][0] = fmaf(xv, w.x, acc[r][0]);
                acc[r][1] = fmaf(xv, w.y, acc[r][1]);
            }
        }
        #pragma unroll
        for (int r = 0; r < 4; r++)
            *(float2*)&g_x[(base+r)*AF + lane*2] = make_float2(acc[r][0], acc[r][1]);
        __syncwarp();
    }
}

// ---------------- P/Q GEMM core: 4 atoms/warp, fp16 output ---------------
__device__ __forceinline__ void pq_gemm_body4(const uint4* sWq, const __half2* sXw,
                                              int base){
    __half2 z = __float2half2_rn(0.f);
    __half2 acc[4][4] = {{z,z,z,z},{z,z,z,z},{z,z,z,z},{z,z,z,z}};
    int lane = threadIdx.x & 31;
    #pragma unroll 4
    for (int kp = 0; kp < 32; kp++){
        uint4 wAu = sWq[(2*kp)*32 + lane];
        uint4 wBu = sWq[(2*kp+1)*32 + lane];
        __half2 wA[4] = {*(__half2*)&wAu.x, *(__half2*)&wAu.y,
                         *(__half2*)&wAu.z, *(__half2*)&wAu.w};
        __half2 wB[4] = {*(__half2*)&wBu.x, *(__half2*)&wBu.y,
                         *(__half2*)&wBu.z, *(__half2*)&wBu.w};
        #pragma unroll
        for (int a = 0; a < 4; a++){
            __half2 ep = sXw[a*33 + kp];
            __half2 eA = __low2half2(ep), eB = __high2half2(ep);
            #pragma unroll
            for (int c = 0; c < 4; c++){
                acc[a][c] = __hfma2(eA, wA[c], acc[a][c]);
                acc[a][c] = __hfma2(eB, wB[c], acc[a][c]);
            }
        }
    }
    #pragma unroll
    for (int a = 0; a < 4; a++){
        uint4 st;
        st.x = *(unsigned*)&acc[a][0];
        st.y = *(unsigned*)&acc[a][1];
        st.z = *(unsigned*)&acc[a][2];
        st.w = *(unsigned*)&acc[a][3];
        __half2* dst = (lane < 16) ? &g_P[(size_t)(base+a)*64 + lane*4]
                                   : &g_Q[(size_t)(base+a)*64 + (lane-16)*4];
        *(uint4*)dst = st;
    }
}

__device__ __forceinline__ void load_pq_weights(uint4* sWq, const float* Wf){
    __half2* sWh = (__half2*)sWq;
    int tid = threadIdx.x;
    for (int i = tid; i < 64*128; i += 256){
        int k = i >> 7, cp = i & 127;
        int c0 = cp*2, c1 = cp*2 + 1;
        float w0 = (c0 < G1) ? Wf[k*G1 + c0] : Wf[(AF + k)*G1 + (c0 - G1)];
        float w1 = (c1 < G1) ? Wf[k*G1 + c1] : Wf[(AF + k)*G1 + (c1 - G1)];
        sWh[k*128 + cp] = __floats2half2_rn(w0, w1);
    }
}

// ---------------- standalone P/Q GEMM (layer 0) ---------------------------
__global__ void __launch_bounds__(256) kPQ2(const float* __restrict__ Wf){
    __shared__ uint4 sWq[64*32];          // 32768 B
    __shared__ __half2 sX[8][4*33];
    int tid = threadIdx.x, wid = tid >> 5, lane = tid & 31;
    load_pq_weights(sWq, Wf);
    __syncthreads();
    int gw = blockIdx.x*8 + wid, nw = gridDim.x*8;
    for (int grp = gw; grp < N_ATOMSC/4; grp += nw){
        int base = grp*4;
        #pragma unroll
        for (int i = lane; i < 128; i += 32){
            int a = i >> 5, kp = i & 31;
            sX[wid][a*33 + kp] = __floats2half2_rn(g_x[(base+a)*AF + kp*2],
                                                   g_x[(base+a)*AF + kp*2 + 1]);
        }
        __syncwarp();
        pq_gemm_body4(sWq, sX[wid], base);
        __syncwarp();
    }
}

// ---------------- fused residual update + next-layer P/Q GEMM ------------
__global__ void __launch_bounds__(256) kUpdatePQ(const float* __restrict__ WfNext){
    __shared__ uint4 sWq[64*32];
    __shared__ __half2 sX[8][4*33];
    int tid = threadIdx.x, wid = tid >> 5, lane = tid & 31;
    load_pq_weights(sWq, WfNext);
    __syncthreads();
    int gw = blockIdx.x*8 + wid, nw = gridDim.x*8;
    for (int grp = gw; grp < N_ATOMSC/4; grp += nw){
        int base = grp*4;
        #pragma unroll
        for (int i = lane; i < 128; i += 32){
            int a = i >> 5, kp = i & 31;
            size_t off = (size_t)(base+a)*AF + kp*2;
            float2 xv = *(const float2*)&g_x[off];
            float2 nv = *(const float2*)&g_ns[off];
            float2 a2 = *(const float2*)&g_a2[kp*2];
            float2 b2 = *(const float2*)&g_b2[kp*2];
            float x0 = softplus_fast(xv.x + fmaf(nv.x, a2.x, b2.x));
            float x1 = softplus_fast(xv.y + fmaf(nv.y, a2.y, b2.y));
            *(float2*)&g_x[off] = make_float2(x0, x1);
            sX[wid][a*33 + kp] = __floats2half2_rn(x0, x1);
        }
        __syncwarp();
        pq_gemm_body4(sWq, sX[wid], base);
        __syncwarp();
    }
}

// ---------------- edge kernel: fp16 P/Q gathers, HADD2 epilogue ----------
__global__ void __launch_bounds__(256, 3) kEdgeH(const int*   __restrict__ NI,
                                                 const float* __restrict__ Wf,
                                                 const float* __restrict__ bf){
    __shared__ uint2 sWq[42*32];                  // 10752 B
    __shared__ __half2 sbh[64];
    __shared__ float sS[G1], sQ[G1];
    __shared__ __align__(16) __half2 sE[8][256];  // 8192 B
    int tid = threadIdx.x, wid = tid >> 5, lane = tid & 31;
    const float* WfE = Wf + 128*G1;
    __half2* sWh = (__half2*)sWq;
    for (int i = tid; i < NBRF*64; i += 256){
        int k = i >> 6, cp = i & 63;
        sWh[k*64 + cp] = __floats2half2_rn(WfE[k*G1 + cp*2], WfE[k*G1 + cp*2 + 1]);
    }
    for (int i = NBRF*64 + tid; i < 42*64; i += 256) sWh[i] = __float2half2_rn(0.f);
    if (tid < 64) sbh[tid] = __floats2half2_rn(bf[tid*2], bf[tid*2+1]);
    if (tid < G1){ sS[tid] = 0.f; sQ[tid] = 0.f; }
    __syncthreads();

    __half2 bb0 = sbh[lane*2], bb1 = sbh[lane*2+1];
    float cs[4] = {0,0,0,0}, cq[4] = {0,0,0,0};

    const uint4* Eh4 = (const uint4*)g_Eh;
    int gw = blockIdx.x*8 + wid, nw = gridDim.x*8;
    uint4 er0, er1;
    if (gw < N_ATOMSC){
        er0 = Eh4[(size_t)gw*64 + lane];
        er1 = Eh4[(size_t)gw*64 + 32 + lane];
    }

    for (int n = gw; n < N_ATOMSC; n += nw){
        ((uint4*)sE[wid])[lane]      = er0;
        ((uint4*)sE[wid])[lane + 32] = er1;
        __syncwarp();
        int nn = n + nw;
        if (nn < N_ATOMSC){
            er0 = Eh4[(size_t)nn*64 + lane];
            er1 = Eh4[(size_t)nn*64 + 32 + lane];
        }

        size_t rb = (size_t)n * 12;
        int4 j0 = *(const int4*)&NI[rb];
        int4 j1 = *(const int4*)&NI[rb + 4];
        int4 j2 = *(const int4*)&NI[rb + 8];
        int jj[12] = {j0.x,j0.y,j0.z,j0.w, j1.x,j1.y,j1.z,j1.w, j2.x,j2.y,j2.z,j2.w};
        uint2 pu = *(const uint2*)&g_P[(size_t)n*64 + lane*2];
        __half2 pqb0 = __hadd2(*(__half2*)&pu.x, bb0);
        __half2 pqb1 = __hadd2(*(__half2*)&pu.y, bb1);

        __half2 z = __float2half2_rn(0.f);
        __half2 acc[12][2];
        #pragma unroll
        for (int r = 0; r < 12; r++){ acc[r][0] = z; acc[r][1] = z; }
        #pragma unroll 3
        for (int kp = 0; kp < 21; kp++){
            uint2 wAu = sWq[(2*kp)*32 + lane];
            uint2 wBu = sWq[(2*kp+1)*32 + lane];
            __half2 wA0 = *(__half2*)&wAu.x, wA1 = *(__half2*)&wAu.y;
            __half2 wB0 = *(__half2*)&wBu.x, wB1 = *(__half2*)&wBu.y;
            #pragma unroll
            for (int r = 0; r < 12; r++){
                __half2 ep = sE[wid][r*21 + kp];
                __half2 eA = __low2half2(ep), eB = __high2half2(ep);
                acc[r][0] = __hfma2(eA, wA0, acc[r][0]);
                acc[r][1] = __hfma2(eA, wA1, acc[r][1]);
                acc[r][0] = __hfma2(eB, wB0, acc[r][0]);
                acc[r][1] = __hfma2(eB, wB1, acc[r][1]);
            }
        }
        #pragma unroll
        for (int r = 0; r < 12; r++){
            uint2 qu = *(const uint2*)&g_Q[(size_t)jj[r]*64 + lane*2];
            __half2 v0 = __hadd2(__hadd2(acc[r][0], pqb0), *(__half2*)&qu.x);
            __half2 v1 = __hadd2(__hadd2(acc[r][1], pqb1), *(__half2*)&qu.y);
            *(uint2*)&g_gated[(rb + r)*(G1/2) + lane*2] =
                make_uint2(*(unsigned*)&v0, *(unsigned*)&v1);
            float2 f0 = __half22float2(v0);
            float2 f1 = __half22float2(v1);
            cs[0] += f0.x; cq[0] = fmaf(f0.x, f0.x, cq[0]);
            cs[1] += f0.y; cq[1] = fmaf(f0.y, f0.y, cq[1]);
            cs[2] += f1.x; cq[2] = fmaf(f1.x, f1.x, cq[2]);
            cs[3] += f1.y; cq[3] = fmaf(f1.y, f1.y, cq[3]);
        }
        __syncwarp();
    }
    atomicAdd(&sS[lane*4+0], cs[0]); atomicAdd(&sQ[lane*4+0], cq[0]);
    atomicAdd(&sS[lane*4+1], cs[1]); atomicAdd(&sQ[lane*4+1], cq[1]);
    atomicAdd(&sS[lane*4+2], cs[2]); atomicAdd(&sQ[lane*4+2], cq[2]);
    atomicAdd(&sS[lane*4+3], cs[3]); atomicAdd(&sQ[lane*4+3], cq[3]);
    __syncthreads();
    if (tid < G1){
        atomicAdd(&g_s1[tid],  sS[tid]);
        atomicAdd(&g_ss1[tid], sQ[tid]);
    }
}

// ---------------- reduce: inline BN1 fold + sigmoid*softplus --------------
__global__ void __launch_bounds__(256) kReduce(const float* __restrict__ gam1,
                                               const float* __restrict__ bet1){
    __shared__ float rs[AF], rq[AF];
    int tid = threadIdx.x;
    int wid = tid >> 5, lane = tid & 31;
    if (tid < AF){ rs[tid] = 0.f; rq[tid] = 0.f; }
    int f2 = lane*2;
    float A1x, A1y, B1x, B1y, A2x, A2y, B2x, B2y;
    {
        const float inv = 1.f / (float)NM;
        #pragma unroll
        for (int t = 0; t < 4; t++){
            int f = (t >> 1) ? (64 + f2 + (t & 1)) : (f2 + (t & 1));
            float m = g_s1[f]*inv;
            float v = g_ss1[f]*inv - m*m;
            float a = gam1[f] * rsqrtf(v + EPSL);
            float bb = bet1[f] - m*a;
            if (t == 0){ A1x = a; B1x = bb; }
            else if (t == 1){ A1y = a; B1y = bb; }
            else if (t == 2){ A2x = a; B2x = bb; }
            else { A2y = a; B2y = bb; }
        }
    }
    __syncthreads();
    float s0=0,s1=0,q0=0,q1=0;
    int gw = blockIdx.x*8 + wid, nw = gridDim.x*8;
    for (int n = gw; n < N_ATOMSC; n += nw){
        const __half2* bh = g_gated + (size_t)n*(M_NBR*(G1/2)) + lane;
        __half2 hf[M_NBR], hc[M_NBR];
        #pragma unroll
        for (int m = 0; m < M_NBR; m++){
            hf[m] = bh[m*64];
            hc[m] = bh[m*64 + 32];
        }
        float a0 = 0.f, a1 = 0.f;
        #pragma unroll
        for (int m = 0; m < M_NBR; m++){
            float2 zf = __half22float2(hf[m]);
            float2 zc = __half22float2(hc[m]);
            float xf0 = fmaf(zf.x, A1x, B1x);
            float xf1 = fmaf(zf.y, A1y, B1y);
            float xc0 = fmaf(zc.x, A2x, B2x);
            float xc1 = fmaf(zc.y, A2y, B2y);
            float sg0 = sigmoid_tanh(xf0);
            float sg1 = sigmoid_tanh(xf1);
            a0 = fmaf(sg0, softplus_fast(xc0), a0);
            a1 = fmaf(sg1, softplus_fast(xc1), a1);
        }
        *(float2*)&g_ns[(size_t)n*AF + f2] = make_float2(a0, a1);
        s0 += a0; q0 = fmaf(a0, a0, q0);
        s1 += a1; q1 = fmaf(a1, a1, q1);
    }
    atomicAdd(&rs[f2],   s0); atomicAdd(&rq[f2],   q0);
    atomicAdd(&rs[f2+1], s1); atomicAdd(&rq[f2+1], q1);
    __syncthreads();
    if (tid < AF){
        atomicAdd(&g_s2[tid],  rs[tid]);
        atomicAdd(&g_ss2[tid], rq[tid]);
    }
}

// ---------------- BN2 finalize + BN1 stat reset ---------------------------
__global__ void kBN2(const float* __restrict__ gam, const float* __restrict__ bet){
    int f = threadIdx.x;
    float inv = 1.f / (float)N_ATOMSC;
    float m = g_s2[f]*inv;
    float v = g_ss2[f]*inv - m*m;
    float a = gam[f] * rsqrtf(v + EPSL);
    g_a2[f] = a;
    g_b2[f] = bet[f] - m*a;
    g_s2[f] = 0.f; g_ss2[f] = 0.f;
    g_s1[f] = 0.f;      g_ss1[f] = 0.f;
    g_s1[f+64] = 0.f;   g_ss1[f+64] = 0.f;
}

// ---------------- plain residual update (last layer) ---------------------
__global__ void __launch_bounds__(256) kUpdate(){
    int i4 = blockIdx.x*256 + threadIdx.x;
    int f = (i4 & 15) * 4;
    float4 xv = *(const float4*)&g_x[i4*4];
    float4 nv = *(const float4*)&g_ns[i4*4];
    float4 a2 = *(const float4*)&g_a2[f];
    float4 b2 = *(const float4*)&g_b2[f];
    float4 o;
    o.x = softplus_fast(xv.x + fmaf(nv.x, a2.x, b2.x));
    o.y = softplus_fast(xv.y + fmaf(nv.y, a2.y, b2.y));
    o.z = softplus_fast(xv.z + fmaf(nv.z, a2.z, b2.z));
    o.w = softplus_fast(xv.w + fmaf(nv.w, a2.w, b2.w));
    *(float4*)&g_x[i4*4] = o;
}

// ---------------- pool + FC + ReLU ---------------------------------------
__global__ void __launch_bounds__(128) kPool(const int* __restrict__ cidx,
                                             const float* __restrict__ Wp,
                                             const float* __restrict__ bp,
                                             float* __restrict__ out){
    __shared__ float sm[AF];
    int c = blockIdx.x, tid = threadIdx.x;
    if (tid < AF){
        float s = 0.f;
        #pragma unroll 5
        for (int a = 0; a < APC; a++){
            int idx = cidx[c*APC + a];
            s += g_x[idx*AF + tid];
        }
        sm[tid] = s * (1.f/(float)APC);
    }
    __syncthreads();
    float acc = bp[tid];
    #pragma unroll 8
    for (int k = 0; k < AF; k++)
        acc = fmaf(sm[k], Wp[k*OUTD + tid], acc);
    out[c*OUTD + tid] = fmaxf(acc, 0.f);
}

// ---------------- launcher ------------------------------------------------
extern "C" void kernel_launch(void* const* d_in, const int* in_sizes, int n_in,
                              void* d_out, int out_size){
    const float* atom_fea = (const float*)d_in[0];
    const float* nbr_fea  = (const float*)d_in[1];
    const int*   nbr_idx  = (const int*)  d_in[2];
    const int*   cidx     = (const int*)  d_in[3];
    const float* W_embed  = (const float*)d_in[4];
    const float* b_embed  = (const float*)d_in[5];
    const float* W_full   = (const float*)d_in[6];
    const float* b_full   = (const float*)d_in[7];
    const float* g1       = (const float*)d_in[8];
    const float* be1      = (const float*)d_in[9];
    const float* g2       = (const float*)d_in[10];
    const float* be2      = (const float*)d_in[11];
    const float* Wp       = (const float*)d_in[12];
    const float* bp       = (const float*)d_in[13];
    float* out = (float*)d_out;

    kEmbedPrep<<<EMB_BLKS + N_ATOMSC, 256>>>(atom_fea, W_embed, b_embed, nbr_fea); // 0
    kPQ2<<<592, 256>>>(W_full);                                                    // 1
    for (int l = 0; l < 3; l++){
        const float* Wf = W_full + (size_t)l * 169 * G1;
        kEdgeH <<<444, 256>>>(nbr_idx, Wf, b_full + l*G1);   // l==0 -> launch 2
        kReduce<<<1184, 256>>>(g1 + l*G1, be1 + l*G1);       // l==0 -> launch 3
        kBN2   <<<1, 64>>>(g2 + l*AF, be2 + l*AF);
        if (l < 2){
            const float* WfN = W_full + (size_t)(l+1) * 169 * G1;
            kUpdatePQ<<<592, 256>>>(WfN);
        } else {
            kUpdate<<<(N_ATOMSC*AF/4)/256, 256>>>();
        }
    }
    kPool<<<NCRY, 128>>>(cidx, Wp, bp, out);
}